// round 5
// baseline (speedup 1.0000x reference)
#include <cuda_runtime.h>
#include <math.h>

// Problem constants
#define KDIM   2048
#define KHD    128
#define KNH    16
#define KBATCH 2
#define KSEQ   2048
#define KQKV   (3 * KNH * KHD)   // 6144
#define KMODEL (KNH * KHD)       // 2048

// Scratch (device globals: allocation-free rule)
__device__ float g_qkv[KBATCH * KSEQ * KQKV];    // [B*S, 6144] : q|k|v heads
__device__ float g_comb[KBATCH * KSEQ * KMODEL]; // [B*S, 2048]

// ---------------------------------------------------------------------------
// SGEMM: C[M,N] = A[M,K] * B[N,K]^T   (both row-major; computes A @ B^T)
// 128x128 block, BK=16, 256 threads, 8x8 per-thread microtile.
// ---------------------------------------------------------------------------
__global__ __launch_bounds__(256) void sgemm_tn(
    const float* __restrict__ A, const float* __restrict__ B,
    float* __restrict__ C, int M, int N, int K)
{
    constexpr int BK = 16;
    constexpr int SPAD = 132;  // padded stride (floats)
    __shared__ float As[BK][SPAD];
    __shared__ float Bs[BK][SPAD];

    const int tid = threadIdx.x;
    const int bm = blockIdx.y * 128;
    const int bn = blockIdx.x * 128;
    const int ty = tid >> 4;        // 0..15
    const int tx = tid & 15;        // 0..15
    const int lrow = tid >> 2;      // 0..63
    const int lcol = (tid & 3) << 2;// 0,4,8,12

    const float* Ap = A + (size_t)(bm + lrow) * K + lcol;
    const float* Bp = B + (size_t)(bn + lrow) * K + lcol;

    float acc[8][8];
    #pragma unroll
    for (int i = 0; i < 8; i++)
        #pragma unroll
        for (int j = 0; j < 8; j++) acc[i][j] = 0.f;

    for (int k0 = 0; k0 < K; k0 += BK) {
        float4 a0 = *(const float4*)(Ap + k0);
        float4 a1 = *(const float4*)(Ap + (size_t)64 * K + k0);
        float4 b0 = *(const float4*)(Bp + k0);
        float4 b1 = *(const float4*)(Bp + (size_t)64 * K + k0);

        As[lcol + 0][lrow] = a0.x; As[lcol + 1][lrow] = a0.y;
        As[lcol + 2][lrow] = a0.z; As[lcol + 3][lrow] = a0.w;
        As[lcol + 0][lrow + 64] = a1.x; As[lcol + 1][lrow + 64] = a1.y;
        As[lcol + 2][lrow + 64] = a1.z; As[lcol + 3][lrow + 64] = a1.w;
        Bs[lcol + 0][lrow] = b0.x; Bs[lcol + 1][lrow] = b0.y;
        Bs[lcol + 2][lrow] = b0.z; Bs[lcol + 3][lrow] = b0.w;
        Bs[lcol + 0][lrow + 64] = b1.x; Bs[lcol + 1][lrow + 64] = b1.y;
        Bs[lcol + 2][lrow + 64] = b1.z; Bs[lcol + 3][lrow + 64] = b1.w;
        __syncthreads();

        #pragma unroll
        for (int k = 0; k < BK; k++) {
            float av[8], bv[8];
            *(float4*)(av)     = *(const float4*)&As[k][ty * 8];
            *(float4*)(av + 4) = *(const float4*)&As[k][ty * 8 + 4];
            *(float4*)(bv)     = *(const float4*)&Bs[k][tx * 8];
            *(float4*)(bv + 4) = *(const float4*)&Bs[k][tx * 8 + 4];
            #pragma unroll
            for (int i = 0; i < 8; i++)
                #pragma unroll
                for (int j = 0; j < 8; j++)
                    acc[i][j] = fmaf(av[i], bv[j], acc[i][j]);
        }
        __syncthreads();
    }

    #pragma unroll
    for (int i = 0; i < 8; i++) {
        float* crow = C + (size_t)(bm + ty * 8 + i) * N + bn + tx * 8;
        float4 c0 = make_float4(acc[i][0], acc[i][1], acc[i][2], acc[i][3]);
        float4 c1 = make_float4(acc[i][4], acc[i][5], acc[i][6], acc[i][7]);
        *(float4*)crow = c0;
        *(float4*)(crow + 4) = c1;
    }
}

// ---------------------------------------------------------------------------
// Flash attention, fp32, online softmax.
// Grid: (S/64, H, B). Block: 256 threads (ty=tid/16, tx=tid&15).
// Q tile 64 rows; KV tiles of 64 keys; D=128.
// QsT/KsT stored transposed [128][72]; Vs row-major [64][132]; Ps [64][68].
// ---------------------------------------------------------------------------
#define FBQ 64
#define FBK 64
#define TPAD 72
#define VPAD 132
#define PPAD 68

__global__ __launch_bounds__(256) void flash_fp32()
{
    extern __shared__ float sm[];
    float* QsT = sm;                       // 128*72
    float* KsT = QsT + KHD * TPAD;         // 128*72
    float* Vs  = KsT + KHD * TPAD;         // 64*132
    float* Ps  = Vs + FBK * VPAD;          // 64*68

    const int tid = threadIdx.x;
    const int qb = blockIdx.x;
    const int h  = blockIdx.y;
    const int b  = blockIdx.z;
    const int q0 = qb * FBQ;

    // ---- Load Q tile transposed into QsT[d][r] ----
    {
        const int lr = tid & 31;    // base row lane
        const int dg = tid >> 5;    // 0..7
        #pragma unroll
        for (int t = 0; t < 8; t++) {
            int r  = lr + 32 * (t & 1);
            int d0 = dg * 4 + (t >> 1) * 32;
            float4 v = *(const float4*)(g_qkv +
                (size_t)(b * KSEQ + q0 + r) * KQKV + h * KHD + d0);
            QsT[(d0 + 0) * TPAD + r] = v.x;
            QsT[(d0 + 1) * TPAD + r] = v.y;
            QsT[(d0 + 2) * TPAD + r] = v.z;
            QsT[(d0 + 3) * TPAD + r] = v.w;
        }
    }

    const int ty = tid >> 4;  // 0..15 -> S rows ty*4.., O rows ty*4..
    const int tx = tid & 15;  // S cols tx*4.., O cols tx*8..

    float o[4][8];
    #pragma unroll
    for (int i = 0; i < 4; i++)
        #pragma unroll
        for (int j = 0; j < 8; j++) o[i][j] = 0.f;
    float mrow[4] = {-INFINITY, -INFINITY, -INFINITY, -INFINITY};
    float lrow[4] = {0.f, 0.f, 0.f, 0.f};
    const float scale = 0.08838834764831845f; // 1/sqrt(128)

    for (int kb = 0; kb < KSEQ / FBK; kb++) {
        const int kbase = kb * FBK;
        __syncthreads();  // prior PV reads done before overwriting K/V (also gates Q on iter 0)

        // ---- Load K tile transposed ----
        {
            const int lr = tid & 31;
            const int dg = tid >> 5;
            #pragma unroll
            for (int t = 0; t < 8; t++) {
                int r  = lr + 32 * (t & 1);
                int d0 = dg * 4 + (t >> 1) * 32;
                float4 v = *(const float4*)(g_qkv +
                    (size_t)(b * KSEQ + kbase + r) * KQKV + (KNH + h) * KHD + d0);
                KsT[(d0 + 0) * TPAD + r] = v.x;
                KsT[(d0 + 1) * TPAD + r] = v.y;
                KsT[(d0 + 2) * TPAD + r] = v.z;
                KsT[(d0 + 3) * TPAD + r] = v.w;
            }
        }
        // ---- Load V tile row-major (coalesced) ----
        {
            const int c0 = tid >> 5;           // 0..7
            const int d4 = (tid & 31) * 4;     // 0..124
            #pragma unroll
            for (int t = 0; t < 8; t++) {
                int c = c0 + t * 8;
                float4 v = *(const float4*)(g_qkv +
                    (size_t)(b * KSEQ + kbase + c) * KQKV + (2 * KNH + h) * KHD + d4);
                *(float4*)&Vs[c * VPAD + d4] = v;
            }
        }
        __syncthreads();

        // ---- S = Q K^T (4x4 per thread), outer-product over k ----
        float s[4][4];
        #pragma unroll
        for (int i = 0; i < 4; i++)
            #pragma unroll
            for (int j = 0; j < 4; j++) s[i][j] = 0.f;

        #pragma unroll 16
        for (int k = 0; k < KHD; k++) {
            float4 qv = *(const float4*)&QsT[k * TPAD + ty * 4];
            float4 kv = *(const float4*)&KsT[k * TPAD + tx * 4];
            float qa[4] = {qv.x, qv.y, qv.z, qv.w};
            float ka[4] = {kv.x, kv.y, kv.z, kv.w};
            #pragma unroll
            for (int i = 0; i < 4; i++)
                #pragma unroll
                for (int j = 0; j < 4; j++)
                    s[i][j] = fmaf(qa[i], ka[j], s[i][j]);
        }

        // ---- Online softmax update ----
        float p[4][4];
        #pragma unroll
        for (int i = 0; i < 4; i++) {
            float mx = -INFINITY;
            #pragma unroll
            for (int j = 0; j < 4; j++) {
                s[i][j] *= scale;
                mx = fmaxf(mx, s[i][j]);
            }
            // reduce across the 16 tx lanes (same ty group within warp)
            #pragma unroll
            for (int m = 1; m < 16; m <<= 1)
                mx = fmaxf(mx, __shfl_xor_sync(0xffffffffu, mx, m));
            float mnew = fmaxf(mrow[i], mx);
            float corr = __expf(mrow[i] - mnew);
            mrow[i] = mnew;
            float rs = 0.f;
            #pragma unroll
            for (int j = 0; j < 4; j++) {
                p[i][j] = __expf(s[i][j] - mnew);
                rs += p[i][j];
            }
            #pragma unroll
            for (int m = 1; m < 16; m <<= 1)
                rs += __shfl_xor_sync(0xffffffffu, rs, m);
            lrow[i] = lrow[i] * corr + rs;
            #pragma unroll
            for (int j = 0; j < 8; j++) o[i][j] *= corr;
            // stage P
            float4 pv = make_float4(p[i][0], p[i][1], p[i][2], p[i][3]);
            *(float4*)&Ps[(ty * 4 + i) * PPAD + tx * 4] = pv;
        }
        __syncthreads();

        // ---- O += P @ V ----
        #pragma unroll 8
        for (int c = 0; c < FBK; c++) {
            float4 v0 = *(const float4*)&Vs[c * VPAD + tx * 8];
            float4 v1 = *(const float4*)&Vs[c * VPAD + tx * 8 + 4];
            #pragma unroll
            for (int i = 0; i < 4; i++) {
                float pv = Ps[(ty * 4 + i) * PPAD + c];
                o[i][0] = fmaf(pv, v0.x, o[i][0]);
                o[i][1] = fmaf(pv, v0.y, o[i][1]);
                o[i][2] = fmaf(pv, v0.z, o[i][2]);
                o[i][3] = fmaf(pv, v0.w, o[i][3]);
                o[i][4] = fmaf(pv, v1.x, o[i][4]);
                o[i][5] = fmaf(pv, v1.y, o[i][5]);
                o[i][6] = fmaf(pv, v1.z, o[i][6]);
                o[i][7] = fmaf(pv, v1.w, o[i][7]);
            }
        }
    }

    // ---- Epilogue: O /= l, write to combined ----
    #pragma unroll
    for (int i = 0; i < 4; i++) {
        float inv = 1.f / lrow[i];
        float* dst = g_comb + (size_t)(b * KSEQ + q0 + ty * 4 + i) * KMODEL
                     + h * KHD + tx * 8;
        float4 c0 = make_float4(o[i][0] * inv, o[i][1] * inv, o[i][2] * inv, o[i][3] * inv);
        float4 c1 = make_float4(o[i][4] * inv, o[i][5] * inv, o[i][6] * inv, o[i][7] * inv);
        *(float4*)dst = c0;
        *(float4*)(dst + 4) = c1;
    }
}

// ---------------------------------------------------------------------------
extern "C" void kernel_launch(void* const* d_in, const int* in_sizes, int n_in,
                              void* d_out, int out_size)
{
    (void)in_sizes; (void)n_in; (void)out_size;
    const float* x     = (const float*)d_in[0];  // [B,S,2048]
    const float* w_qkv = (const float*)d_in[1];  // [6144,2048]
    const float* w_out = (const float*)d_in[2];  // [2048,2048]
    float* out = (float*)d_out;                  // [B,S,2048]

    float* qkv_p;  cudaGetSymbolAddress((void**)&qkv_p,  g_qkv);
    float* comb_p; cudaGetSymbolAddress((void**)&comb_p, g_comb);

    // 1) QKV projection: [4096,2048] @ [6144,2048]^T -> [4096,6144]
    {
        dim3 grid(KQKV / 128, (KBATCH * KSEQ) / 128);
        sgemm_tn<<<grid, 256>>>(x, w_qkv, qkv_p, KBATCH * KSEQ, KQKV, KDIM);
    }

    // 2) Flash attention -> combined [4096,2048]
    {
        int smem = (2 * KHD * TPAD + FBK * VPAD + FBQ * PPAD) * (int)sizeof(float);
        cudaFuncSetAttribute(flash_fp32,
                             cudaFuncAttributeMaxDynamicSharedMemorySize, smem);
        dim3 grid(KSEQ / FBQ, KNH, KBATCH);
        flash_fp32<<<grid, 256, smem>>>();
    }

    // 3) Output projection: [4096,2048] @ [2048,2048]^T -> [4096,2048]
    {
        dim3 grid(KMODEL / 128, (KBATCH * KSEQ) / 128);
        sgemm_tn<<<grid, 256>>>(comb_p, w_out, out, KBATCH * KSEQ, KMODEL, KDIM);
    }
}

// round 10
// speedup vs baseline: 1.4998x; 1.4998x over previous
#include <cuda_runtime.h>
#include <cuda_bf16.h>
#include <math.h>
#include <stdint.h>

// Problem constants
#define KDIM   2048
#define KHD    128
#define KNH    16
#define KBATCH 2
#define KSEQ   2048
#define KQKV   6144
#define KMODEL 2048
#define KROWS  (KBATCH * KSEQ)   // 4096
#define KBIG   (3 * KDIM)        // 6144 : [hi | lo | hi] / [hi | hi | lo] split-K

// Scratch (device globals: allocation-free rule)
__device__ float g_qkv[(size_t)KROWS * KQKV];                           // fp32 qkv for flash
__device__ __align__(16) __nv_bfloat16 g_xbig[(size_t)KROWS * KBIG];    // A-side split of x
__device__ __align__(16) __nv_bfloat16 g_wqkvbig[(size_t)KQKV * KBIG];  // B-side split of w_qkv
__device__ __align__(16) __nv_bfloat16 g_combbig[(size_t)KROWS * KBIG]; // A-side split of attn out
__device__ __align__(16) __nv_bfloat16 g_woutbig[(size_t)KMODEL * KBIG];// B-side split of w_out

// ---------------------------------------------------------------------------
// Split fp32 -> bf16 hi/lo, K-concatenated.
// aside=1: [hi | lo | hi]   (A operand)
// aside=0: [hi | hi | lo]   (B operand)
// ---------------------------------------------------------------------------
__global__ __launch_bounds__(256) void split_bf16(
    const float* __restrict__ src, __nv_bfloat16* __restrict__ dst,
    int total4, int K, int aside)
{
    int idx = blockIdx.x * blockDim.x + threadIdx.x;
    if (idx >= total4) return;
    int e = idx * 4;
    int r = e / K;
    int k = e - r * K;
    float4 v = *(const float4*)(src + (size_t)e);
    float a[4] = {v.x, v.y, v.z, v.w};
    unsigned short hs[4], ls[4];
#pragma unroll
    for (int i = 0; i < 4; i++) {
        __nv_bfloat16 h = __float2bfloat16(a[i]);
        hs[i] = __bfloat16_as_ushort(h);
        ls[i] = __bfloat16_as_ushort(__float2bfloat16(a[i] - __bfloat162float(h)));
    }
    uint2 hp, lp;
    hp.x = (uint32_t)hs[0] | ((uint32_t)hs[1] << 16);
    hp.y = (uint32_t)hs[2] | ((uint32_t)hs[3] << 16);
    lp.x = (uint32_t)ls[0] | ((uint32_t)ls[1] << 16);
    lp.y = (uint32_t)ls[2] | ((uint32_t)ls[3] << 16);
    size_t rb = (size_t)r * (3 * K) + k;
    if (aside) {
        *(uint2*)(dst + rb)         = hp;
        *(uint2*)(dst + rb + K)     = lp;
        *(uint2*)(dst + rb + 2 * K) = hp;
    } else {
        *(uint2*)(dst + rb)         = hp;
        *(uint2*)(dst + rb + K)     = hp;
        *(uint2*)(dst + rb + 2 * K) = lp;
    }
}

// ---------------------------------------------------------------------------
// HMMA bf16 GEMM: C[M,N] = A'[M,KBIG] * B'[N,KBIG]^T  (split-K encoded)
// CTA 128x128, BK=64, 2-stage cp.async, SW128 swizzled smem, ldmatrix + 
// mma.sync.m16n8k16 (base-target instructions only: sm_80+, works on sm_103).
// 256 threads = 8 warps (4 x 2), warp tile 32x64, fp32 accumulators.
// ---------------------------------------------------------------------------
#define BM 128
#define BN 128
#define BK 64
#define NCHUNK (KBIG / BK)       // 96
#define TILE_BYTES 16384         // 128 rows * 128B
#define STAGE_BYTES 32768
#define GEMM_SMEM   65536

__device__ __forceinline__ uint32_t smem_u32(const void* p) {
    uint32_t a;
    asm("{ .reg .u64 t; cvta.to.shared.u64 t, %1; cvt.u32.u64 %0, t; }"
        : "=r"(a) : "l"(p));
    return a;
}
__device__ __forceinline__ uint32_t sw128(uint32_t o) { return o ^ ((o >> 3) & 0x70); }

__device__ __forceinline__ void ldsm_x4(uint32_t addr, uint32_t& r0, uint32_t& r1,
                                        uint32_t& r2, uint32_t& r3) {
    asm volatile("ldmatrix.sync.aligned.m8n8.x4.shared.b16 {%0,%1,%2,%3}, [%4];"
                 : "=r"(r0), "=r"(r1), "=r"(r2), "=r"(r3) : "r"(addr));
}

__device__ __forceinline__ void mma_bf16(float& c0, float& c1, float& c2, float& c3,
                                         uint32_t a0, uint32_t a1, uint32_t a2, uint32_t a3,
                                         uint32_t b0, uint32_t b1) {
    asm volatile(
        "mma.sync.aligned.m16n8k16.row.col.f32.bf16.bf16.f32 "
        "{%0,%1,%2,%3}, {%4,%5,%6,%7}, {%8,%9}, {%0,%1,%2,%3};"
        : "+f"(c0), "+f"(c1), "+f"(c2), "+f"(c3)
        : "r"(a0), "r"(a1), "r"(a2), "r"(a3), "r"(b0), "r"(b1));
}

__global__ __launch_bounds__(256, 2) void gemm_bf16split(
    const __nv_bfloat16* __restrict__ A, const __nv_bfloat16* __restrict__ B,
    float* __restrict__ C, int N)
{
    extern __shared__ char smem[];
    const uint32_t sbase = smem_u32(smem);
    const int tid = threadIdx.x;
    const int wid = tid >> 5;
    const int lane = tid & 31;
    const int wm = wid >> 1;       // 0..3 : 32 rows each
    const int wn = wid & 1;        // 0..1 : 64 cols each
    const int bm = blockIdx.y * BM;
    const int bn = blockIdx.x * BN;

    // cp.async one BK=64 chunk (A:128 rows, B:128 rows; 128B/row) into stage
    auto load_chunk = [&](int c) {
        const uint32_t st = (uint32_t)(c & 1) * STAGE_BYTES;
        const char* Asrc = (const char*)(A + (size_t)bm * KBIG) + (size_t)c * 128;
        const char* Bsrc = (const char*)(B + (size_t)bn * KBIG) + (size_t)c * 128;
#pragma unroll
        for (int i = 0; i < 4; i++) {
            int u = i * 256 + tid;
            int row = u >> 3, ku = u & 7;
            uint32_t dst = sbase + st + sw128((uint32_t)(row * 128 + ku * 16));
            const char* src = Asrc + (size_t)row * (KBIG * 2) + ku * 16;
            asm volatile("cp.async.cg.shared.global [%0], [%1], 16;"
                         :: "r"(dst), "l"(src) : "memory");
        }
#pragma unroll
        for (int i = 0; i < 4; i++) {
            int u = i * 256 + tid;
            int row = u >> 3, ku = u & 7;
            uint32_t dst = sbase + st + TILE_BYTES + sw128((uint32_t)(row * 128 + ku * 16));
            const char* src = Bsrc + (size_t)row * (KBIG * 2) + ku * 16;
            asm volatile("cp.async.cg.shared.global [%0], [%1], 16;"
                         :: "r"(dst), "l"(src) : "memory");
        }
        asm volatile("cp.async.commit_group;" ::: "memory");
    };

    float acc[2][8][4];
#pragma unroll
    for (int mt = 0; mt < 2; mt++)
#pragma unroll
        for (int nt = 0; nt < 8; nt++)
#pragma unroll
            for (int q = 0; q < 4; q++) acc[mt][nt][q] = 0.f;

    load_chunk(0);
    load_chunk(1);

    const int lrow = lane & 15;    // ldmatrix row within 16
    const int lsel = lane >> 4;    // 0: k-chunk lo16B, 1: hi16B

#pragma unroll 1
    for (int c = 0; c < NCHUNK; c++) {
        if (c + 1 < NCHUNK) { asm volatile("cp.async.wait_group 1;" ::: "memory"); }
        else                { asm volatile("cp.async.wait_group 0;" ::: "memory"); }
        __syncthreads();

        const uint32_t ab = sbase + (uint32_t)(c & 1) * STAGE_BYTES;
        const uint32_t bb = ab + TILE_BYTES;
        const int m0 = wm * 32;
        const int n0 = wn * 64;

#pragma unroll
        for (int ks = 0; ks < 4; ks++) {
            const int chk = 2 * ks + lsel;          // 16B chunk within 128B row
            uint32_t a[2][4];
#pragma unroll
            for (int mt = 0; mt < 2; mt++) {
                int r = m0 + mt * 16 + lrow;
                uint32_t addr = ab + sw128((uint32_t)(r * 128 + chk * 16));
                ldsm_x4(addr, a[mt][0], a[mt][1], a[mt][2], a[mt][3]);
            }
            uint32_t blo[8], bhi[8];
#pragma unroll
            for (int p = 0; p < 4; p++) {           // pairs of n8 tiles
                int r = n0 + p * 16 + lrow;
                uint32_t addr = bb + sw128((uint32_t)(r * 128 + chk * 16));
                uint32_t r0, r1, r2, r3;
                ldsm_x4(addr, r0, r1, r2, r3);
                blo[2 * p] = r0; blo[2 * p + 1] = r1;
                bhi[2 * p] = r2; bhi[2 * p + 1] = r3;
            }
#pragma unroll
            for (int mt = 0; mt < 2; mt++)
#pragma unroll
                for (int nt = 0; nt < 8; nt++)
                    mma_bf16(acc[mt][nt][0], acc[mt][nt][1], acc[mt][nt][2], acc[mt][nt][3],
                             a[mt][0], a[mt][1], a[mt][2], a[mt][3],
                             blo[nt], bhi[nt]);
        }

        __syncthreads();
        if (c + 2 < NCHUNK) load_chunk(c + 2);
    }

    // Epilogue: thread holds (m = base + lane/4 [+8], n = base + 2*(lane&3) [+1])
    const int mbase = bm + wm * 32 + (lane >> 2);
    const int nbase = bn + wn * 64 + 2 * (lane & 3);
#pragma unroll
    for (int mt = 0; mt < 2; mt++) {
#pragma unroll
        for (int nt = 0; nt < 8; nt++) {
            float* p0 = C + (size_t)(mbase + mt * 16) * N + nbase + nt * 8;
            float* p1 = C + (size_t)(mbase + mt * 16 + 8) * N + nbase + nt * 8;
            *(float2*)p0 = make_float2(acc[mt][nt][0], acc[mt][nt][1]);
            *(float2*)p1 = make_float2(acc[mt][nt][2], acc[mt][nt][3]);
        }
    }
}

// ---------------------------------------------------------------------------
// Flash attention, fp32, online softmax (unchanged math).
// Epilogue writes split-bf16 [hi|lo|hi] rows directly into g_combbig.
// ---------------------------------------------------------------------------
#define FBQ 64
#define FBK 64
#define TPAD 72
#define VPAD 132
#define PPAD 68

__global__ __launch_bounds__(256) void flash_fp32()
{
    extern __shared__ float sm[];
    float* QsT = sm;                       // 128*72
    float* KsT = QsT + KHD * TPAD;         // 128*72
    float* Vs  = KsT + KHD * TPAD;         // 64*132
    float* Ps  = Vs + FBK * VPAD;          // 64*68

    const int tid = threadIdx.x;
    const int qb = blockIdx.x;
    const int h  = blockIdx.y;
    const int b  = blockIdx.z;
    const int q0 = qb * FBQ;

    {
        const int lr = tid & 31;
        const int dg = tid >> 5;
        #pragma unroll
        for (int t = 0; t < 8; t++) {
            int r  = lr + 32 * (t & 1);
            int d0 = dg * 4 + (t >> 1) * 32;
            float4 v = *(const float4*)(g_qkv +
                (size_t)(b * KSEQ + q0 + r) * KQKV + h * KHD + d0);
            QsT[(d0 + 0) * TPAD + r] = v.x;
            QsT[(d0 + 1) * TPAD + r] = v.y;
            QsT[(d0 + 2) * TPAD + r] = v.z;
            QsT[(d0 + 3) * TPAD + r] = v.w;
        }
    }

    const int ty = tid >> 4;
    const int tx = tid & 15;

    float o[4][8];
    #pragma unroll
    for (int i = 0; i < 4; i++)
        #pragma unroll
        for (int j = 0; j < 8; j++) o[i][j] = 0.f;
    float mrow[4] = {-INFINITY, -INFINITY, -INFINITY, -INFINITY};
    float lrow[4] = {0.f, 0.f, 0.f, 0.f};
    const float scale = 0.08838834764831845f;

    for (int kb = 0; kb < KSEQ / FBK; kb++) {
        const int kbase = kb * FBK;
        __syncthreads();

        {
            const int lr = tid & 31;
            const int dg = tid >> 5;
            #pragma unroll
            for (int t = 0; t < 8; t++) {
                int r  = lr + 32 * (t & 1);
                int d0 = dg * 4 + (t >> 1) * 32;
                float4 v = *(const float4*)(g_qkv +
                    (size_t)(b * KSEQ + kbase + r) * KQKV + (KNH + h) * KHD + d0);
                KsT[(d0 + 0) * TPAD + r] = v.x;
                KsT[(d0 + 1) * TPAD + r] = v.y;
                KsT[(d0 + 2) * TPAD + r] = v.z;
                KsT[(d0 + 3) * TPAD + r] = v.w;
            }
        }
        {
            const int c0 = tid >> 5;
            const int d4 = (tid & 31) * 4;
            #pragma unroll
            for (int t = 0; t < 8; t++) {
                int c = c0 + t * 8;
                float4 v = *(const float4*)(g_qkv +
                    (size_t)(b * KSEQ + kbase + c) * KQKV + (2 * KNH + h) * KHD + d4);
                *(float4*)&Vs[c * VPAD + d4] = v;
            }
        }
        __syncthreads();

        float s[4][4];
        #pragma unroll
        for (int i = 0; i < 4; i++)
            #pragma unroll
            for (int j = 0; j < 4; j++) s[i][j] = 0.f;

        #pragma unroll 16
        for (int k = 0; k < KHD; k++) {
            float4 qv = *(const float4*)&QsT[k * TPAD + ty * 4];
            float4 kv = *(const float4*)&KsT[k * TPAD + tx * 4];
            float qa[4] = {qv.x, qv.y, qv.z, qv.w};
            float ka[4] = {kv.x, kv.y, kv.z, kv.w};
            #pragma unroll
            for (int i = 0; i < 4; i++)
                #pragma unroll
                for (int j = 0; j < 4; j++)
                    s[i][j] = fmaf(qa[i], ka[j], s[i][j]);
        }

        float p[4][4];
        #pragma unroll
        for (int i = 0; i < 4; i++) {
            float mx = -INFINITY;
            #pragma unroll
            for (int j = 0; j < 4; j++) {
                s[i][j] *= scale;
                mx = fmaxf(mx, s[i][j]);
            }
            #pragma unroll
            for (int m = 1; m < 16; m <<= 1)
                mx = fmaxf(mx, __shfl_xor_sync(0xffffffffu, mx, m));
            float mnew = fmaxf(mrow[i], mx);
            float corr = __expf(mrow[i] - mnew);
            mrow[i] = mnew;
            float rs = 0.f;
            #pragma unroll
            for (int j = 0; j < 4; j++) {
                p[i][j] = __expf(s[i][j] - mnew);
                rs += p[i][j];
            }
            #pragma unroll
            for (int m = 1; m < 16; m <<= 1)
                rs += __shfl_xor_sync(0xffffffffu, rs, m);
            lrow[i] = lrow[i] * corr + rs;
            #pragma unroll
            for (int j = 0; j < 8; j++) o[i][j] *= corr;
            float4 pv = make_float4(p[i][0], p[i][1], p[i][2], p[i][3]);
            *(float4*)&Ps[(ty * 4 + i) * PPAD + tx * 4] = pv;
        }
        __syncthreads();

        #pragma unroll 8
        for (int c = 0; c < FBK; c++) {
            float4 v0 = *(const float4*)&Vs[c * VPAD + tx * 8];
            float4 v1 = *(const float4*)&Vs[c * VPAD + tx * 8 + 4];
            #pragma unroll
            for (int i = 0; i < 4; i++) {
                float pv = Ps[(ty * 4 + i) * PPAD + c];
                o[i][0] = fmaf(pv, v0.x, o[i][0]);
                o[i][1] = fmaf(pv, v0.y, o[i][1]);
                o[i][2] = fmaf(pv, v0.z, o[i][2]);
                o[i][3] = fmaf(pv, v0.w, o[i][3]);
                o[i][4] = fmaf(pv, v1.x, o[i][4]);
                o[i][5] = fmaf(pv, v1.y, o[i][5]);
                o[i][6] = fmaf(pv, v1.z, o[i][6]);
                o[i][7] = fmaf(pv, v1.w, o[i][7]);
            }
        }
    }

    // Epilogue: O /= l, write split-bf16 [hi|lo|hi] into g_combbig
    #pragma unroll
    for (int i = 0; i < 4; i++) {
        float inv = 1.f / lrow[i];
        size_t row = (size_t)(b * KSEQ + q0 + ty * 4 + i);
        __nv_bfloat16* dst = g_combbig + row * KBIG + h * KHD + tx * 8;
        unsigned short hs[8], ls[8];
        #pragma unroll
        for (int j = 0; j < 8; j++) {
            float v = o[i][j] * inv;
            __nv_bfloat16 hv = __float2bfloat16(v);
            hs[j] = __bfloat16_as_ushort(hv);
            ls[j] = __bfloat16_as_ushort(__float2bfloat16(v - __bfloat162float(hv)));
        }
        uint4 hp, lp;
        hp.x = (uint32_t)hs[0] | ((uint32_t)hs[1] << 16);
        hp.y = (uint32_t)hs[2] | ((uint32_t)hs[3] << 16);
        hp.z = (uint32_t)hs[4] | ((uint32_t)hs[5] << 16);
        hp.w = (uint32_t)hs[6] | ((uint32_t)hs[7] << 16);
        lp.x = (uint32_t)ls[0] | ((uint32_t)ls[1] << 16);
        lp.y = (uint32_t)ls[2] | ((uint32_t)ls[3] << 16);
        lp.z = (uint32_t)ls[4] | ((uint32_t)ls[5] << 16);
        lp.w = (uint32_t)ls[6] | ((uint32_t)ls[7] << 16);
        *(uint4*)(dst)            = hp;
        *(uint4*)(dst + KDIM)     = lp;
        *(uint4*)(dst + 2 * KDIM) = hp;
    }
}

// ---------------------------------------------------------------------------
extern "C" void kernel_launch(void* const* d_in, const int* in_sizes, int n_in,
                              void* d_out, int out_size)
{
    (void)in_sizes; (void)n_in; (void)out_size;
    const float* x     = (const float*)d_in[0];  // [B,S,2048]
    const float* w_qkv = (const float*)d_in[1];  // [6144,2048]
    const float* w_out = (const float*)d_in[2];  // [2048,2048]
    float* out = (float*)d_out;                  // [B,S,2048]

    float* qkv_p;           cudaGetSymbolAddress((void**)&qkv_p,  g_qkv);
    __nv_bfloat16* xb_p;    cudaGetSymbolAddress((void**)&xb_p,   g_xbig);
    __nv_bfloat16* wq_p;    cudaGetSymbolAddress((void**)&wq_p,   g_wqkvbig);
    __nv_bfloat16* cb_p;    cudaGetSymbolAddress((void**)&cb_p,   g_combbig);
    __nv_bfloat16* wo_p;    cudaGetSymbolAddress((void**)&wo_p,   g_woutbig);

    // 0) Split fp32 -> bf16 hi/lo (K-concatenated)
    {
        int t4;
        t4 = KROWS * KDIM / 4;
        split_bf16<<<(t4 + 255) / 256, 256>>>(x, xb_p, t4, KDIM, 1);
        t4 = KQKV * KDIM / 4;
        split_bf16<<<(t4 + 255) / 256, 256>>>(w_qkv, wq_p, t4, KDIM, 0);
        t4 = KMODEL * KDIM / 4;
        split_bf16<<<(t4 + 255) / 256, 256>>>(w_out, wo_p, t4, KDIM, 0);
    }

    cudaFuncSetAttribute(gemm_bf16split,
                         cudaFuncAttributeMaxDynamicSharedMemorySize, GEMM_SMEM);

    // 1) QKV projection (HMMA): [4096,6144]x[6144,6144]^T -> fp32 g_qkv
    {
        dim3 grid(KQKV / BN, KROWS / BM);
        gemm_bf16split<<<grid, 256, GEMM_SMEM>>>(xb_p, wq_p, qkv_p, KQKV);
    }

    // 2) Flash attention -> split-bf16 g_combbig
    {
        int smem = (2 * KHD * TPAD + FBK * VPAD + FBQ * PPAD) * (int)sizeof(float);
        cudaFuncSetAttribute(flash_fp32,
                             cudaFuncAttributeMaxDynamicSharedMemorySize, smem);
        dim3 grid(KSEQ / FBQ, KNH, KBATCH);
        flash_fp32<<<grid, 256, smem>>>();
    }

    // 3) Output projection (HMMA): [4096,6144]x[2048,6144]^T -> out
    {
        dim3 grid(KMODEL / BN, KROWS / BM);
        gemm_bf16split<<<grid, 256, GEMM_SMEM>>>(cb_p, wo_p, out, KMODEL);
    }
}

// round 11
// speedup vs baseline: 4.2859x; 2.8576x over previous
#include <cuda_runtime.h>
#include <cuda_bf16.h>
#include <cuda_fp16.h>
#include <math.h>
#include <stdint.h>

// Problem constants
#define KDIM   2048
#define KHD    128
#define KNH    16
#define KBATCH 2
#define KSEQ   2048
#define KQKV   6144
#define KMODEL 2048
#define KROWS  (KBATCH * KSEQ)   // 4096
#define KBIG   (3 * KDIM)        // 6144 : [hi | lo | hi] / [hi | hi | lo] split-K

// Scratch (device globals: allocation-free rule)
__device__ __align__(16) __half g_qkv16[(size_t)KROWS * KQKV];          // fp16 qkv for flash
__device__ __align__(16) __nv_bfloat16 g_xbig[(size_t)KROWS * KBIG];    // A-side split of x
__device__ __align__(16) __nv_bfloat16 g_wqkvbig[(size_t)KQKV * KBIG];  // B-side split of w_qkv
__device__ __align__(16) __nv_bfloat16 g_combbig[(size_t)KROWS * KBIG]; // A-side split of attn out
__device__ __align__(16) __nv_bfloat16 g_woutbig[(size_t)KMODEL * KBIG];// B-side split of w_out

// ---------------------------------------------------------------------------
// Split fp32 -> bf16 hi/lo, K-concatenated.
// ---------------------------------------------------------------------------
__global__ __launch_bounds__(256) void split_bf16(
    const float* __restrict__ src, __nv_bfloat16* __restrict__ dst,
    int total4, int K, int aside)
{
    int idx = blockIdx.x * blockDim.x + threadIdx.x;
    if (idx >= total4) return;
    int e = idx * 4;
    int r = e / K;
    int k = e - r * K;
    float4 v = *(const float4*)(src + (size_t)e);
    float a[4] = {v.x, v.y, v.z, v.w};
    unsigned short hs[4], ls[4];
#pragma unroll
    for (int i = 0; i < 4; i++) {
        __nv_bfloat16 h = __float2bfloat16(a[i]);
        hs[i] = __bfloat16_as_ushort(h);
        ls[i] = __bfloat16_as_ushort(__float2bfloat16(a[i] - __bfloat162float(h)));
    }
    uint2 hp, lp;
    hp.x = (uint32_t)hs[0] | ((uint32_t)hs[1] << 16);
    hp.y = (uint32_t)hs[2] | ((uint32_t)hs[3] << 16);
    lp.x = (uint32_t)ls[0] | ((uint32_t)ls[1] << 16);
    lp.y = (uint32_t)ls[2] | ((uint32_t)ls[3] << 16);
    size_t rb = (size_t)r * (3 * K) + k;
    if (aside) {
        *(uint2*)(dst + rb)         = hp;
        *(uint2*)(dst + rb + K)     = lp;
        *(uint2*)(dst + rb + 2 * K) = hp;
    } else {
        *(uint2*)(dst + rb)         = hp;
        *(uint2*)(dst + rb + K)     = hp;
        *(uint2*)(dst + rb + 2 * K) = lp;
    }
}

// ---------------------------------------------------------------------------
// Common helpers
// ---------------------------------------------------------------------------
__device__ __forceinline__ uint32_t smem_u32(const void* p) {
    uint32_t a;
    asm("{ .reg .u64 t; cvta.to.shared.u64 t, %1; cvt.u32.u64 %0, t; }"
        : "=r"(a) : "l"(p));
    return a;
}
__device__ __forceinline__ uint32_t sw128(uint32_t o) { return o ^ ((o >> 3) & 0x70); }

__device__ __forceinline__ void ldsm_x4(uint32_t addr, uint32_t& r0, uint32_t& r1,
                                        uint32_t& r2, uint32_t& r3) {
    asm volatile("ldmatrix.sync.aligned.m8n8.x4.shared.b16 {%0,%1,%2,%3}, [%4];"
                 : "=r"(r0), "=r"(r1), "=r"(r2), "=r"(r3) : "r"(addr));
}
__device__ __forceinline__ void ldsm_x4t(uint32_t addr, uint32_t& r0, uint32_t& r1,
                                         uint32_t& r2, uint32_t& r3) {
    asm volatile("ldmatrix.sync.aligned.m8n8.x4.trans.shared.b16 {%0,%1,%2,%3}, [%4];"
                 : "=r"(r0), "=r"(r1), "=r"(r2), "=r"(r3) : "r"(addr));
}

__device__ __forceinline__ void mma_bf16(float& c0, float& c1, float& c2, float& c3,
                                         uint32_t a0, uint32_t a1, uint32_t a2, uint32_t a3,
                                         uint32_t b0, uint32_t b1) {
    asm volatile(
        "mma.sync.aligned.m16n8k16.row.col.f32.bf16.bf16.f32 "
        "{%0,%1,%2,%3}, {%4,%5,%6,%7}, {%8,%9}, {%0,%1,%2,%3};"
        : "+f"(c0), "+f"(c1), "+f"(c2), "+f"(c3)
        : "r"(a0), "r"(a1), "r"(a2), "r"(a3), "r"(b0), "r"(b1));
}
__device__ __forceinline__ void mma_f16(float& c0, float& c1, float& c2, float& c3,
                                        uint32_t a0, uint32_t a1, uint32_t a2, uint32_t a3,
                                        uint32_t b0, uint32_t b1) {
    asm volatile(
        "mma.sync.aligned.m16n8k16.row.col.f32.f16.f16.f32 "
        "{%0,%1,%2,%3}, {%4,%5,%6,%7}, {%8,%9}, {%0,%1,%2,%3};"
        : "+f"(c0), "+f"(c1), "+f"(c2), "+f"(c3)
        : "r"(a0), "r"(a1), "r"(a2), "r"(a3), "r"(b0), "r"(b1));
}
__device__ __forceinline__ float ex2f(float x) {
    float y;
    asm("ex2.approx.ftz.f32 %0, %1;" : "=f"(y) : "f"(x));
    return y;
}
#define CPA16(dst, src) \
    asm volatile("cp.async.cg.shared.global [%0], [%1], 16;" :: "r"(dst), "l"(src) : "memory")

// ---------------------------------------------------------------------------
// HMMA bf16 GEMM: C = A'[M,KBIG] * B'[N,KBIG]^T  (split-K encoded).
// Output either fp32 (Cf) or fp16 (Ch).
// ---------------------------------------------------------------------------
#define BM 128
#define BN 128
#define BK 64
#define NCHUNK (KBIG / BK)       // 96
#define TILE_BYTES 16384
#define STAGE_BYTES 32768
#define GEMM_SMEM   65536

__global__ __launch_bounds__(256, 2) void gemm_bf16split(
    const __nv_bfloat16* __restrict__ A, const __nv_bfloat16* __restrict__ B,
    float* __restrict__ Cf, __half* __restrict__ Ch, int N)
{
    extern __shared__ char smem[];
    const uint32_t sbase = smem_u32(smem);
    const int tid = threadIdx.x;
    const int wid = tid >> 5;
    const int lane = tid & 31;
    const int wm = wid >> 1;
    const int wn = wid & 1;
    const int bm = blockIdx.y * BM;
    const int bn = blockIdx.x * BN;

    auto load_chunk = [&](int c) {
        const uint32_t st = (uint32_t)(c & 1) * STAGE_BYTES;
        const char* Asrc = (const char*)(A + (size_t)bm * KBIG) + (size_t)c * 128;
        const char* Bsrc = (const char*)(B + (size_t)bn * KBIG) + (size_t)c * 128;
#pragma unroll
        for (int i = 0; i < 4; i++) {
            int u = i * 256 + tid;
            int row = u >> 3, ku = u & 7;
            uint32_t dst = sbase + st + sw128((uint32_t)(row * 128 + ku * 16));
            CPA16(dst, Asrc + (size_t)row * (KBIG * 2) + ku * 16);
        }
#pragma unroll
        for (int i = 0; i < 4; i++) {
            int u = i * 256 + tid;
            int row = u >> 3, ku = u & 7;
            uint32_t dst = sbase + st + TILE_BYTES + sw128((uint32_t)(row * 128 + ku * 16));
            CPA16(dst, Bsrc + (size_t)row * (KBIG * 2) + ku * 16);
        }
        asm volatile("cp.async.commit_group;" ::: "memory");
    };

    float acc[2][8][4];
#pragma unroll
    for (int mt = 0; mt < 2; mt++)
#pragma unroll
        for (int nt = 0; nt < 8; nt++)
#pragma unroll
            for (int q = 0; q < 4; q++) acc[mt][nt][q] = 0.f;

    load_chunk(0);
    load_chunk(1);

    const int lrow = lane & 15;
    const int lsel = lane >> 4;

#pragma unroll 1
    for (int c = 0; c < NCHUNK; c++) {
        if (c + 1 < NCHUNK) { asm volatile("cp.async.wait_group 1;" ::: "memory"); }
        else                { asm volatile("cp.async.wait_group 0;" ::: "memory"); }
        __syncthreads();

        const uint32_t ab = sbase + (uint32_t)(c & 1) * STAGE_BYTES;
        const uint32_t bb = ab + TILE_BYTES;
        const int m0 = wm * 32;
        const int n0 = wn * 64;

#pragma unroll
        for (int ks = 0; ks < 4; ks++) {
            const int chk = 2 * ks + lsel;
            uint32_t a[2][4];
#pragma unroll
            for (int mt = 0; mt < 2; mt++) {
                int r = m0 + mt * 16 + lrow;
                ldsm_x4(ab + sw128((uint32_t)(r * 128 + chk * 16)),
                        a[mt][0], a[mt][1], a[mt][2], a[mt][3]);
            }
            uint32_t blo[8], bhi[8];
#pragma unroll
            for (int p = 0; p < 4; p++) {
                int r = n0 + p * 16 + lrow;
                uint32_t r0, r1, r2, r3;
                ldsm_x4(bb + sw128((uint32_t)(r * 128 + chk * 16)), r0, r1, r2, r3);
                blo[2 * p] = r0; blo[2 * p + 1] = r1;
                bhi[2 * p] = r2; bhi[2 * p + 1] = r3;
            }
#pragma unroll
            for (int mt = 0; mt < 2; mt++)
#pragma unroll
                for (int nt = 0; nt < 8; nt++)
                    mma_bf16(acc[mt][nt][0], acc[mt][nt][1], acc[mt][nt][2], acc[mt][nt][3],
                             a[mt][0], a[mt][1], a[mt][2], a[mt][3],
                             blo[nt], bhi[nt]);
        }

        __syncthreads();
        if (c + 2 < NCHUNK) load_chunk(c + 2);
    }

    const int mbase = bm + wm * 32 + (lane >> 2);
    const int nbase = bn + wn * 64 + 2 * (lane & 3);
    if (Ch) {
#pragma unroll
        for (int mt = 0; mt < 2; mt++)
#pragma unroll
            for (int nt = 0; nt < 8; nt++) {
                __half* p0 = Ch + (size_t)(mbase + mt * 16) * N + nbase + nt * 8;
                __half* p1 = Ch + (size_t)(mbase + mt * 16 + 8) * N + nbase + nt * 8;
                *(__half2*)p0 = __floats2half2_rn(acc[mt][nt][0], acc[mt][nt][1]);
                *(__half2*)p1 = __floats2half2_rn(acc[mt][nt][2], acc[mt][nt][3]);
            }
    } else {
#pragma unroll
        for (int mt = 0; mt < 2; mt++)
#pragma unroll
            for (int nt = 0; nt < 8; nt++) {
                float* p0 = Cf + (size_t)(mbase + mt * 16) * N + nbase + nt * 8;
                float* p1 = Cf + (size_t)(mbase + mt * 16 + 8) * N + nbase + nt * 8;
                *(float2*)p0 = make_float2(acc[mt][nt][0], acc[mt][nt][1]);
                *(float2*)p1 = make_float2(acc[mt][nt][2], acc[mt][nt][3]);
            }
    }
}

// ---------------------------------------------------------------------------
// Flash attention, fp16 HMMA + f16x2 exp2, online softmax.
// Grid (S/64, H, B), 128 threads = 4 warps, warp = 16 q rows.
// smem: Q [2 chunks x 8KB] | K 2 stages x 16KB | V 2 stages x 16KB = 80KB.
// Row-sum l accumulated via a constant fp16 ones-column B fragment.
// ---------------------------------------------------------------------------
#define FBQ 64
#define FBK 64
#define NKT (KSEQ / FBK)         // 32
#define FQ_OFF 0
#define FK_OFF 16384
#define FV_OFF 49152
#define FLASH_SMEM 81920

__global__ __launch_bounds__(128) void flash_f16()
{
    extern __shared__ char smem[];
    const uint32_t sbase = smem_u32(smem);
    const int tid = threadIdx.x;
    const int wid = tid >> 5;     // warp 0..3 -> q rows wid*16
    const int lane = tid & 31;
    const int qb = blockIdx.x;
    const int h  = blockIdx.y;
    const int b  = blockIdx.z;
    const int q0 = qb * FBQ;

    const char* qkvb = (const char*)g_qkv16;
    const size_t rowB = (size_t)KQKV * 2;   // bytes per qkv row

    // ---- Q load (8 cp.async/thread) into 2 swizzled chunks ----
    {
        const size_t base = (size_t)(b * KSEQ + q0) * rowB + (size_t)h * 256;
#pragma unroll
        for (int i = 0; i < 8; i++) {
            int u = i * 128 + tid;
            int row = u >> 4, c16 = u & 15;
            uint32_t dst = sbase + FQ_OFF + (uint32_t)(c16 >> 3) * 8192
                         + sw128((uint32_t)(row * 128 + (c16 & 7) * 16));
            CPA16(dst, qkvb + base + (size_t)row * rowB + c16 * 16);
        }
    }
    // ---- K/V tile load ----
    auto load_kv = [&](int kb) {
        const uint32_t st = (uint32_t)(kb & 1) * 16384;
        const size_t kbase = (size_t)(b * KSEQ + kb * FBK) * rowB + (size_t)(KNH + h) * 256;
        const size_t vbase = (size_t)(b * KSEQ + kb * FBK) * rowB + (size_t)(2 * KNH + h) * 256;
#pragma unroll
        for (int i = 0; i < 8; i++) {
            int u = i * 128 + tid;
            int row = u >> 4, c16 = u & 15;
            uint32_t off = (uint32_t)(c16 >> 3) * 8192
                         + sw128((uint32_t)(row * 128 + (c16 & 7) * 16));
            CPA16(sbase + FK_OFF + st + off, qkvb + kbase + (size_t)row * rowB + c16 * 16);
        }
#pragma unroll
        for (int i = 0; i < 8; i++) {
            int u = i * 128 + tid;
            int row = u >> 4, c16 = u & 15;
            uint32_t off = (uint32_t)(c16 >> 3) * 8192
                         + sw128((uint32_t)(row * 128 + (c16 & 7) * 16));
            CPA16(sbase + FV_OFF + st + off, qkvb + vbase + (size_t)row * rowB + c16 * 16);
        }
        asm volatile("cp.async.commit_group;" ::: "memory");
    };

    load_kv(0);                   // group 0 (includes Q)
    load_kv(1);                   // group 1

    // o accums: 16 d-tiles + ones tile (index 16)
    float o[17][4];
#pragma unroll
    for (int t = 0; t < 17; t++)
#pragma unroll
        for (int q = 0; q < 4; q++) o[t][q] = 0.f;
    float m0 = -1e30f, m1 = -1e30f;

    const float sl2e = 1.4426950408889634f * 0.08838834764831845f; // log2(e)/sqrt(128)
    const int lrow = lane & 15;
    const int lsel = lane >> 4;
    const uint32_t ones_b = (lane < 4) ? 0x3C003C00u : 0u;   // fp16 1.0 pair, n-col 0 only

#pragma unroll 1
    for (int kb = 0; kb < NKT; kb++) {
        if (kb + 1 < NKT) { asm volatile("cp.async.wait_group 1;" ::: "memory"); }
        else              { asm volatile("cp.async.wait_group 0;" ::: "memory"); }
        __syncthreads();

        const uint32_t kbuf = sbase + FK_OFF + (uint32_t)(kb & 1) * 16384;
        const uint32_t vbuf = sbase + FV_OFF + (uint32_t)(kb & 1) * 16384;
        const uint32_t qbuf = sbase + FQ_OFF;

        // ---- S = Q K^T : m16 x n64, 8 k-steps ----
        float s[8][4];
#pragma unroll
        for (int nt = 0; nt < 8; nt++)
#pragma unroll
            for (int q = 0; q < 4; q++) s[nt][q] = 0.f;

#pragma unroll
        for (int ks = 0; ks < 8; ks++) {
            const uint32_t chko = (uint32_t)(ks >> 2) * 8192;
            const int chk = 2 * (ks & 3) + lsel;
            uint32_t a0, a1, a2, a3;
            {
                int r = wid * 16 + lrow;
                ldsm_x4(qbuf + chko + sw128((uint32_t)(r * 128 + chk * 16)), a0, a1, a2, a3);
            }
            uint32_t blo[8], bhi[8];
#pragma unroll
            for (int p = 0; p < 4; p++) {
                int r = p * 16 + lrow;
                uint32_t r0, r1, r2, r3;
                ldsm_x4(kbuf + chko + sw128((uint32_t)(r * 128 + chk * 16)), r0, r1, r2, r3);
                blo[2 * p] = r0; blo[2 * p + 1] = r1;
                bhi[2 * p] = r2; bhi[2 * p + 1] = r3;
            }
#pragma unroll
            for (int nt = 0; nt < 8; nt++)
                mma_f16(s[nt][0], s[nt][1], s[nt][2], s[nt][3],
                        a0, a1, a2, a3, blo[nt], bhi[nt]);
        }

        // ---- Online softmax (base-2 logits u = s * log2e/sqrt(D)) ----
        float mx0 = -1e30f, mx1 = -1e30f;
#pragma unroll
        for (int nt = 0; nt < 8; nt++) {
            s[nt][0] *= sl2e; s[nt][1] *= sl2e;
            s[nt][2] *= sl2e; s[nt][3] *= sl2e;
            mx0 = fmaxf(mx0, fmaxf(s[nt][0], s[nt][1]));
            mx1 = fmaxf(mx1, fmaxf(s[nt][2], s[nt][3]));
        }
        mx0 = fmaxf(mx0, __shfl_xor_sync(0xffffffffu, mx0, 1));
        mx0 = fmaxf(mx0, __shfl_xor_sync(0xffffffffu, mx0, 2));
        mx1 = fmaxf(mx1, __shfl_xor_sync(0xffffffffu, mx1, 1));
        mx1 = fmaxf(mx1, __shfl_xor_sync(0xffffffffu, mx1, 2));
        const float mn0 = fmaxf(m0, mx0);
        const float mn1 = fmaxf(m1, mx1);
        const float corr0 = ex2f(m0 - mn0);
        const float corr1 = ex2f(m1 - mn1);
        m0 = mn0; m1 = mn1;
#pragma unroll
        for (int t = 0; t < 17; t++) {
            o[t][0] *= corr0; o[t][1] *= corr0;
            o[t][2] *= corr1; o[t][3] *= corr1;
        }
        // p = exp2(u - m) in f16x2, directly usable as MMA A fragments
        uint32_t p01[8], p23[8];
#pragma unroll
        for (int nt = 0; nt < 8; nt++) {
            __half2 h0 = h2exp2(__floats2half2_rn(s[nt][0] - mn0, s[nt][1] - mn0));
            __half2 h1 = h2exp2(__floats2half2_rn(s[nt][2] - mn1, s[nt][3] - mn1));
            p01[nt] = *(uint32_t*)&h0;
            p23[nt] = *(uint32_t*)&h1;
        }

        // ---- O += P V : 4 k-steps (keys), B via ldmatrix.trans on V[key][d] ----
        const int grp  = lane >> 3;            // address group 0..3
        const int glr  = lane & 7;
#pragma unroll
        for (int ks = 0; ks < 4; ks++) {
            const uint32_t a0 = p01[2 * ks],     a1 = p23[2 * ks];
            const uint32_t a2 = p01[2 * ks + 1], a3 = p23[2 * ks + 1];
            const int key = 16 * ks + (grp & 1) * 8 + glr;
#pragma unroll
            for (int pp = 0; pp < 8; pp++) {
                const int d = pp * 16 + (grp >> 1) * 8;
                const uint32_t addr = vbuf + (uint32_t)(d >> 6) * 8192
                                    + sw128((uint32_t)(key * 128 + (d & 63) * 2));
                uint32_t r0, r1, r2, r3;
                ldsm_x4t(addr, r0, r1, r2, r3);
                mma_f16(o[2 * pp][0], o[2 * pp][1], o[2 * pp][2], o[2 * pp][3],
                        a0, a1, a2, a3, r0, r1);
                mma_f16(o[2 * pp + 1][0], o[2 * pp + 1][1], o[2 * pp + 1][2], o[2 * pp + 1][3],
                        a0, a1, a2, a3, r2, r3);
            }
            mma_f16(o[16][0], o[16][1], o[16][2], o[16][3],
                    a0, a1, a2, a3, ones_b, ones_b);
        }

        __syncthreads();
        if (kb + 2 < NKT) load_kv(kb + 2);
    }

    // ---- Epilogue: l from ones column (quad leader), write split-bf16 ----
    const int src = lane & ~3;
    const float l0 = __shfl_sync(0xffffffffu, o[16][0], src);
    const float l1 = __shfl_sync(0xffffffffu, o[16][2], src);
    const float inv0 = 1.f / l0;
    const float inv1 = 1.f / l1;

    const int gr0 = b * KSEQ + q0 + wid * 16 + (lane >> 2);
    const int col0 = h * KHD + 2 * (lane & 3);
#pragma unroll
    for (int t = 0; t < 16; t++) {
#pragma unroll
        for (int rr = 0; rr < 2; rr++) {
            float v0 = o[t][2 * rr + 0] * (rr ? inv1 : inv0);
            float v1 = o[t][2 * rr + 1] * (rr ? inv1 : inv0);
            __nv_bfloat16 h0 = __float2bfloat16(v0);
            __nv_bfloat16 h1 = __float2bfloat16(v1);
            __nv_bfloat16 l0b = __float2bfloat16(v0 - __bfloat162float(h0));
            __nv_bfloat16 l1b = __float2bfloat16(v1 - __bfloat162float(h1));
            uint32_t hp = (uint32_t)__bfloat16_as_ushort(h0)
                        | ((uint32_t)__bfloat16_as_ushort(h1) << 16);
            uint32_t lp = (uint32_t)__bfloat16_as_ushort(l0b)
                        | ((uint32_t)__bfloat16_as_ushort(l1b) << 16);
            __nv_bfloat16* dst = g_combbig + (size_t)(gr0 + rr * 8) * KBIG + col0 + t * 8;
            *(uint32_t*)(dst)            = hp;
            *(uint32_t*)(dst + KDIM)     = lp;
            *(uint32_t*)(dst + 2 * KDIM) = hp;
        }
    }
}

// ---------------------------------------------------------------------------
extern "C" void kernel_launch(void* const* d_in, const int* in_sizes, int n_in,
                              void* d_out, int out_size)
{
    (void)in_sizes; (void)n_in; (void)out_size;
    const float* x     = (const float*)d_in[0];
    const float* w_qkv = (const float*)d_in[1];
    const float* w_out = (const float*)d_in[2];
    float* out = (float*)d_out;

    __half* qkv16_p;     cudaGetSymbolAddress((void**)&qkv16_p, g_qkv16);
    __nv_bfloat16* xb_p; cudaGetSymbolAddress((void**)&xb_p,   g_xbig);
    __nv_bfloat16* wq_p; cudaGetSymbolAddress((void**)&wq_p,   g_wqkvbig);
    __nv_bfloat16* cb_p; cudaGetSymbolAddress((void**)&cb_p,   g_combbig);
    __nv_bfloat16* wo_p; cudaGetSymbolAddress((void**)&wo_p,   g_woutbig);

    // 0) Split fp32 -> bf16 hi/lo (K-concatenated)
    {
        int t4;
        t4 = KROWS * KDIM / 4;
        split_bf16<<<(t4 + 255) / 256, 256>>>(x, xb_p, t4, KDIM, 1);
        t4 = KQKV * KDIM / 4;
        split_bf16<<<(t4 + 255) / 256, 256>>>(w_qkv, wq_p, t4, KDIM, 0);
        t4 = KMODEL * KDIM / 4;
        split_bf16<<<(t4 + 255) / 256, 256>>>(w_out, wo_p, t4, KDIM, 0);
    }

    cudaFuncSetAttribute(gemm_bf16split,
                         cudaFuncAttributeMaxDynamicSharedMemorySize, GEMM_SMEM);

    // 1) QKV projection (HMMA) -> fp16 g_qkv16
    {
        dim3 grid(KQKV / BN, KROWS / BM);
        gemm_bf16split<<<grid, 256, GEMM_SMEM>>>(xb_p, wq_p, nullptr, qkv16_p, KQKV);
    }

    // 2) Flash attention (fp16 HMMA) -> split-bf16 g_combbig
    {
        cudaFuncSetAttribute(flash_f16,
                             cudaFuncAttributeMaxDynamicSharedMemorySize, FLASH_SMEM);
        dim3 grid(KSEQ / FBQ, KNH, KBATCH);
        flash_f16<<<grid, 128, FLASH_SMEM>>>();
    }

    // 3) Output projection (HMMA) -> fp32 out
    {
        dim3 grid(KMODEL / BN, KROWS / BM);
        gemm_bf16split<<<grid, 256, GEMM_SMEM>>>(cb_p, wo_p, out, nullptr, KMODEL);
    }
}

// round 12
// speedup vs baseline: 7.2438x; 1.6901x over previous
#include <cuda_runtime.h>
#include <cuda_bf16.h>
#include <cuda_fp16.h>
#include <math.h>
#include <stdint.h>

// Problem constants
#define KDIM   2048
#define KHD    128
#define KNH    16
#define KBATCH 2
#define KSEQ   2048
#define KQKV   6144
#define KMODEL 2048
#define KROWS  (KBATCH * KSEQ)   // 4096
#define KBIG   (3 * KDIM)        // 6144 : split-K encoding for out-proj

// Scratch (device globals: allocation-free rule)
__device__ __align__(16) __half g_qkv16[(size_t)KROWS * KQKV];          // fp16 qkv for flash
__device__ __align__(16) __half g_x16[(size_t)KROWS * KDIM];            // fp16 x
__device__ __align__(16) __half g_wq16[(size_t)KQKV * KDIM];            // fp16 w_qkv
__device__ __align__(16) __nv_bfloat16 g_combbig[(size_t)KROWS * KBIG]; // A-side split of attn out
__device__ __align__(16) __nv_bfloat16 g_woutbig[(size_t)KMODEL * KBIG];// B-side split of w_out

// ---------------------------------------------------------------------------
// fp32 -> fp16 convert (contiguous)
// ---------------------------------------------------------------------------
__global__ __launch_bounds__(256) void conv_f16(
    const float* __restrict__ src, __half* __restrict__ dst, int total4)
{
    int idx = blockIdx.x * blockDim.x + threadIdx.x;
    if (idx >= total4) return;
    float4 v = *(const float4*)(src + (size_t)idx * 4);
    __half2 h0 = __floats2half2_rn(v.x, v.y);
    __half2 h1 = __floats2half2_rn(v.z, v.w);
    uint2 p;
    p.x = *(uint32_t*)&h0;
    p.y = *(uint32_t*)&h1;
    *(uint2*)(dst + (size_t)idx * 4) = p;
}

// ---------------------------------------------------------------------------
// Split fp32 -> bf16 hi/lo, K-concatenated (B operand: [hi | hi | lo]).
// ---------------------------------------------------------------------------
__global__ __launch_bounds__(256) void split_bf16(
    const float* __restrict__ src, __nv_bfloat16* __restrict__ dst,
    int total4, int K)
{
    int idx = blockIdx.x * blockDim.x + threadIdx.x;
    if (idx >= total4) return;
    int e = idx * 4;
    int r = e / K;
    int k = e - r * K;
    float4 v = *(const float4*)(src + (size_t)e);
    float a[4] = {v.x, v.y, v.z, v.w};
    unsigned short hs[4], ls[4];
#pragma unroll
    for (int i = 0; i < 4; i++) {
        __nv_bfloat16 h = __float2bfloat16(a[i]);
        hs[i] = __bfloat16_as_ushort(h);
        ls[i] = __bfloat16_as_ushort(__float2bfloat16(a[i] - __bfloat162float(h)));
    }
    uint2 hp, lp;
    hp.x = (uint32_t)hs[0] | ((uint32_t)hs[1] << 16);
    hp.y = (uint32_t)hs[2] | ((uint32_t)hs[3] << 16);
    lp.x = (uint32_t)ls[0] | ((uint32_t)ls[1] << 16);
    lp.y = (uint32_t)ls[2] | ((uint32_t)ls[3] << 16);
    size_t rb = (size_t)r * (3 * K) + k;
    *(uint2*)(dst + rb)         = hp;
    *(uint2*)(dst + rb + K)     = hp;
    *(uint2*)(dst + rb + 2 * K) = lp;
}

// ---------------------------------------------------------------------------
// Common helpers
// ---------------------------------------------------------------------------
__device__ __forceinline__ uint32_t smem_u32(const void* p) {
    uint32_t a;
    asm("{ .reg .u64 t; cvta.to.shared.u64 t, %1; cvt.u32.u64 %0, t; }"
        : "=r"(a) : "l"(p));
    return a;
}
__device__ __forceinline__ uint32_t sw128(uint32_t o) { return o ^ ((o >> 3) & 0x70); }

__device__ __forceinline__ void ldsm_x4(uint32_t addr, uint32_t& r0, uint32_t& r1,
                                        uint32_t& r2, uint32_t& r3) {
    asm volatile("ldmatrix.sync.aligned.m8n8.x4.shared.b16 {%0,%1,%2,%3}, [%4];"
                 : "=r"(r0), "=r"(r1), "=r"(r2), "=r"(r3) : "r"(addr));
}
__device__ __forceinline__ void ldsm_x4t(uint32_t addr, uint32_t& r0, uint32_t& r1,
                                         uint32_t& r2, uint32_t& r3) {
    asm volatile("ldmatrix.sync.aligned.m8n8.x4.trans.shared.b16 {%0,%1,%2,%3}, [%4];"
                 : "=r"(r0), "=r"(r1), "=r"(r2), "=r"(r3) : "r"(addr));
}

__device__ __forceinline__ void mma_bf16(float& c0, float& c1, float& c2, float& c3,
                                         uint32_t a0, uint32_t a1, uint32_t a2, uint32_t a3,
                                         uint32_t b0, uint32_t b1) {
    asm volatile(
        "mma.sync.aligned.m16n8k16.row.col.f32.bf16.bf16.f32 "
        "{%0,%1,%2,%3}, {%4,%5,%6,%7}, {%8,%9}, {%0,%1,%2,%3};"
        : "+f"(c0), "+f"(c1), "+f"(c2), "+f"(c3)
        : "r"(a0), "r"(a1), "r"(a2), "r"(a3), "r"(b0), "r"(b1));
}
__device__ __forceinline__ void mma_f16(float& c0, float& c1, float& c2, float& c3,
                                        uint32_t a0, uint32_t a1, uint32_t a2, uint32_t a3,
                                        uint32_t b0, uint32_t b1) {
    asm volatile(
        "mma.sync.aligned.m16n8k16.row.col.f32.f16.f16.f32 "
        "{%0,%1,%2,%3}, {%4,%5,%6,%7}, {%8,%9}, {%0,%1,%2,%3};"
        : "+f"(c0), "+f"(c1), "+f"(c2), "+f"(c3)
        : "r"(a0), "r"(a1), "r"(a2), "r"(a3), "r"(b0), "r"(b1));
}
__device__ __forceinline__ float ex2f(float x) {
    float y;
    asm("ex2.approx.ftz.f32 %0, %1;" : "=f"(y) : "f"(x));
    return y;
}
#define CPA16(dst, src) \
    asm volatile("cp.async.cg.shared.global [%0], [%1], 16;" :: "r"(dst), "l"(src) : "memory")

// ---------------------------------------------------------------------------
// HMMA GEMM: C = A[M,K] * B[N,K]^T, 16-bit operands (fp16 or bf16).
// CTA 128x128, BK=64, 2-stage cp.async, SW128 swizzled smem, m16n8k16.
// Output fp32 (Cf) or fp16 (Ch).
// ---------------------------------------------------------------------------
#define BM 128
#define BN 128
#define BK 64
#define TILE_BYTES 16384
#define STAGE_BYTES 32768
#define GEMM_SMEM   65536

template <bool USE_F16>
__global__ __launch_bounds__(256, 2) void gemm_hmma(
    const uint16_t* __restrict__ A, const uint16_t* __restrict__ B,
    float* __restrict__ Cf, __half* __restrict__ Ch, int N, int K)
{
    extern __shared__ char smem[];
    const uint32_t sbase = smem_u32(smem);
    const int tid = threadIdx.x;
    const int wid = tid >> 5;
    const int lane = tid & 31;
    const int wm = wid >> 1;
    const int wn = wid & 1;
    const int bm = blockIdx.y * BM;
    const int bn = blockIdx.x * BN;
    const int nchunk = K / BK;
    const size_t rowB = (size_t)K * 2;

    auto load_chunk = [&](int c) {
        const uint32_t st = (uint32_t)(c & 1) * STAGE_BYTES;
        const char* Asrc = (const char*)(A + (size_t)bm * K) + (size_t)c * 128;
        const char* Bsrc = (const char*)(B + (size_t)bn * K) + (size_t)c * 128;
#pragma unroll
        for (int i = 0; i < 4; i++) {
            int u = i * 256 + tid;
            int row = u >> 3, ku = u & 7;
            uint32_t dst = sbase + st + sw128((uint32_t)(row * 128 + ku * 16));
            CPA16(dst, Asrc + (size_t)row * rowB + ku * 16);
        }
#pragma unroll
        for (int i = 0; i < 4; i++) {
            int u = i * 256 + tid;
            int row = u >> 3, ku = u & 7;
            uint32_t dst = sbase + st + TILE_BYTES + sw128((uint32_t)(row * 128 + ku * 16));
            CPA16(dst, Bsrc + (size_t)row * rowB + ku * 16);
        }
        asm volatile("cp.async.commit_group;" ::: "memory");
    };

    float acc[2][8][4];
#pragma unroll
    for (int mt = 0; mt < 2; mt++)
#pragma unroll
        for (int nt = 0; nt < 8; nt++)
#pragma unroll
            for (int q = 0; q < 4; q++) acc[mt][nt][q] = 0.f;

    load_chunk(0);
    load_chunk(1);

    const int lrow = lane & 15;
    const int lsel = lane >> 4;

#pragma unroll 1
    for (int c = 0; c < nchunk; c++) {
        if (c + 1 < nchunk) { asm volatile("cp.async.wait_group 1;" ::: "memory"); }
        else                { asm volatile("cp.async.wait_group 0;" ::: "memory"); }
        __syncthreads();

        const uint32_t ab = sbase + (uint32_t)(c & 1) * STAGE_BYTES;
        const uint32_t bb = ab + TILE_BYTES;
        const int m0 = wm * 32;
        const int n0 = wn * 64;

#pragma unroll
        for (int ks = 0; ks < 4; ks++) {
            const int chk = 2 * ks + lsel;
            uint32_t a[2][4];
#pragma unroll
            for (int mt = 0; mt < 2; mt++) {
                int r = m0 + mt * 16 + lrow;
                ldsm_x4(ab + sw128((uint32_t)(r * 128 + chk * 16)),
                        a[mt][0], a[mt][1], a[mt][2], a[mt][3]);
            }
            uint32_t blo[8], bhi[8];
#pragma unroll
            for (int p = 0; p < 4; p++) {
                int r = n0 + p * 16 + lrow;
                uint32_t r0, r1, r2, r3;
                ldsm_x4(bb + sw128((uint32_t)(r * 128 + chk * 16)), r0, r1, r2, r3);
                blo[2 * p] = r0; blo[2 * p + 1] = r1;
                bhi[2 * p] = r2; bhi[2 * p + 1] = r3;
            }
#pragma unroll
            for (int mt = 0; mt < 2; mt++)
#pragma unroll
                for (int nt = 0; nt < 8; nt++) {
                    if (USE_F16)
                        mma_f16(acc[mt][nt][0], acc[mt][nt][1], acc[mt][nt][2], acc[mt][nt][3],
                                a[mt][0], a[mt][1], a[mt][2], a[mt][3], blo[nt], bhi[nt]);
                    else
                        mma_bf16(acc[mt][nt][0], acc[mt][nt][1], acc[mt][nt][2], acc[mt][nt][3],
                                 a[mt][0], a[mt][1], a[mt][2], a[mt][3], blo[nt], bhi[nt]);
                }
        }

        __syncthreads();
        if (c + 2 < nchunk) load_chunk(c + 2);
    }

    const int mbase = bm + wm * 32 + (lane >> 2);
    const int nbase = bn + wn * 64 + 2 * (lane & 3);
    if (Ch) {
#pragma unroll
        for (int mt = 0; mt < 2; mt++)
#pragma unroll
            for (int nt = 0; nt < 8; nt++) {
                __half* p0 = Ch + (size_t)(mbase + mt * 16) * N + nbase + nt * 8;
                __half* p1 = Ch + (size_t)(mbase + mt * 16 + 8) * N + nbase + nt * 8;
                *(__half2*)p0 = __floats2half2_rn(acc[mt][nt][0], acc[mt][nt][1]);
                *(__half2*)p1 = __floats2half2_rn(acc[mt][nt][2], acc[mt][nt][3]);
            }
    } else {
#pragma unroll
        for (int mt = 0; mt < 2; mt++)
#pragma unroll
            for (int nt = 0; nt < 8; nt++) {
                float* p0 = Cf + (size_t)(mbase + mt * 16) * N + nbase + nt * 8;
                float* p1 = Cf + (size_t)(mbase + mt * 16 + 8) * N + nbase + nt * 8;
                *(float2*)p0 = make_float2(acc[mt][nt][0], acc[mt][nt][1]);
                *(float2*)p1 = make_float2(acc[mt][nt][2], acc[mt][nt][3]);
            }
    }
}

// ---------------------------------------------------------------------------
// Flash attention, fp16 HMMA + f16x2 exp2, online softmax.
// Grid (S/64, H, B), 128 threads = 4 warps, warp = 16 q rows.
// ---------------------------------------------------------------------------
#define FBQ 64
#define FBK 64
#define NKT (KSEQ / FBK)         // 32
#define FQ_OFF 0
#define FK_OFF 16384
#define FV_OFF 49152
#define FLASH_SMEM 81920

__global__ __launch_bounds__(128) void flash_f16()
{
    extern __shared__ char smem[];
    const uint32_t sbase = smem_u32(smem);
    const int tid = threadIdx.x;
    const int wid = tid >> 5;
    const int lane = tid & 31;
    const int qb = blockIdx.x;
    const int h  = blockIdx.y;
    const int b  = blockIdx.z;
    const int q0 = qb * FBQ;

    const char* qkvb = (const char*)g_qkv16;
    const size_t rowB = (size_t)KQKV * 2;

    {
        const size_t base = (size_t)(b * KSEQ + q0) * rowB + (size_t)h * 256;
#pragma unroll
        for (int i = 0; i < 8; i++) {
            int u = i * 128 + tid;
            int row = u >> 4, c16 = u & 15;
            uint32_t dst = sbase + FQ_OFF + (uint32_t)(c16 >> 3) * 8192
                         + sw128((uint32_t)(row * 128 + (c16 & 7) * 16));
            CPA16(dst, qkvb + base + (size_t)row * rowB + c16 * 16);
        }
    }
    auto load_kv = [&](int kb) {
        const uint32_t st = (uint32_t)(kb & 1) * 16384;
        const size_t kbase = (size_t)(b * KSEQ + kb * FBK) * rowB + (size_t)(KNH + h) * 256;
        const size_t vbase = (size_t)(b * KSEQ + kb * FBK) * rowB + (size_t)(2 * KNH + h) * 256;
#pragma unroll
        for (int i = 0; i < 8; i++) {
            int u = i * 128 + tid;
            int row = u >> 4, c16 = u & 15;
            uint32_t off = (uint32_t)(c16 >> 3) * 8192
                         + sw128((uint32_t)(row * 128 + (c16 & 7) * 16));
            CPA16(sbase + FK_OFF + st + off, qkvb + kbase + (size_t)row * rowB + c16 * 16);
        }
#pragma unroll
        for (int i = 0; i < 8; i++) {
            int u = i * 128 + tid;
            int row = u >> 4, c16 = u & 15;
            uint32_t off = (uint32_t)(c16 >> 3) * 8192
                         + sw128((uint32_t)(row * 128 + (c16 & 7) * 16));
            CPA16(sbase + FV_OFF + st + off, qkvb + vbase + (size_t)row * rowB + c16 * 16);
        }
        asm volatile("cp.async.commit_group;" ::: "memory");
    };

    load_kv(0);
    load_kv(1);

    float o[17][4];
#pragma unroll
    for (int t = 0; t < 17; t++)
#pragma unroll
        for (int q = 0; q < 4; q++) o[t][q] = 0.f;
    float m0 = -1e30f, m1 = -1e30f;

    const float sl2e = 1.4426950408889634f * 0.08838834764831845f;
    const int lrow = lane & 15;
    const int lsel = lane >> 4;
    const uint32_t ones_b = (lane < 4) ? 0x3C003C00u : 0u;

#pragma unroll 1
    for (int kb = 0; kb < NKT; kb++) {
        if (kb + 1 < NKT) { asm volatile("cp.async.wait_group 1;" ::: "memory"); }
        else              { asm volatile("cp.async.wait_group 0;" ::: "memory"); }
        __syncthreads();

        const uint32_t kbuf = sbase + FK_OFF + (uint32_t)(kb & 1) * 16384;
        const uint32_t vbuf = sbase + FV_OFF + (uint32_t)(kb & 1) * 16384;
        const uint32_t qbuf = sbase + FQ_OFF;

        float s[8][4];
#pragma unroll
        for (int nt = 0; nt < 8; nt++)
#pragma unroll
            for (int q = 0; q < 4; q++) s[nt][q] = 0.f;

#pragma unroll
        for (int ks = 0; ks < 8; ks++) {
            const uint32_t chko = (uint32_t)(ks >> 2) * 8192;
            const int chk = 2 * (ks & 3) + lsel;
            uint32_t a0, a1, a2, a3;
            {
                int r = wid * 16 + lrow;
                ldsm_x4(qbuf + chko + sw128((uint32_t)(r * 128 + chk * 16)), a0, a1, a2, a3);
            }
            uint32_t blo[8], bhi[8];
#pragma unroll
            for (int p = 0; p < 4; p++) {
                int r = p * 16 + lrow;
                uint32_t r0, r1, r2, r3;
                ldsm_x4(kbuf + chko + sw128((uint32_t)(r * 128 + chk * 16)), r0, r1, r2, r3);
                blo[2 * p] = r0; blo[2 * p + 1] = r1;
                bhi[2 * p] = r2; bhi[2 * p + 1] = r3;
            }
#pragma unroll
            for (int nt = 0; nt < 8; nt++)
                mma_f16(s[nt][0], s[nt][1], s[nt][2], s[nt][3],
                        a0, a1, a2, a3, blo[nt], bhi[nt]);
        }

        float mx0 = -1e30f, mx1 = -1e30f;
#pragma unroll
        for (int nt = 0; nt < 8; nt++) {
            s[nt][0] *= sl2e; s[nt][1] *= sl2e;
            s[nt][2] *= sl2e; s[nt][3] *= sl2e;
            mx0 = fmaxf(mx0, fmaxf(s[nt][0], s[nt][1]));
            mx1 = fmaxf(mx1, fmaxf(s[nt][2], s[nt][3]));
        }
        mx0 = fmaxf(mx0, __shfl_xor_sync(0xffffffffu, mx0, 1));
        mx0 = fmaxf(mx0, __shfl_xor_sync(0xffffffffu, mx0, 2));
        mx1 = fmaxf(mx1, __shfl_xor_sync(0xffffffffu, mx1, 1));
        mx1 = fmaxf(mx1, __shfl_xor_sync(0xffffffffu, mx1, 2));
        const float mn0 = fmaxf(m0, mx0);
        const float mn1 = fmaxf(m1, mx1);
        const float corr0 = ex2f(m0 - mn0);
        const float corr1 = ex2f(m1 - mn1);
        m0 = mn0; m1 = mn1;
#pragma unroll
        for (int t = 0; t < 17; t++) {
            o[t][0] *= corr0; o[t][1] *= corr0;
            o[t][2] *= corr1; o[t][3] *= corr1;
        }
        uint32_t p01[8], p23[8];
#pragma unroll
        for (int nt = 0; nt < 8; nt++) {
            __half2 h0 = h2exp2(__floats2half2_rn(s[nt][0] - mn0, s[nt][1] - mn0));
            __half2 h1 = h2exp2(__floats2half2_rn(s[nt][2] - mn1, s[nt][3] - mn1));
            p01[nt] = *(uint32_t*)&h0;
            p23[nt] = *(uint32_t*)&h1;
        }

        const int grp  = lane >> 3;
        const int glr  = lane & 7;
#pragma unroll
        for (int ks = 0; ks < 4; ks++) {
            const uint32_t a0 = p01[2 * ks],     a1 = p23[2 * ks];
            const uint32_t a2 = p01[2 * ks + 1], a3 = p23[2 * ks + 1];
            const int key = 16 * ks + (grp & 1) * 8 + glr;
#pragma unroll
            for (int pp = 0; pp < 8; pp++) {
                const int d = pp * 16 + (grp >> 1) * 8;
                const uint32_t addr = vbuf + (uint32_t)(d >> 6) * 8192
                                    + sw128((uint32_t)(key * 128 + (d & 63) * 2));
                uint32_t r0, r1, r2, r3;
                ldsm_x4t(addr, r0, r1, r2, r3);
                mma_f16(o[2 * pp][0], o[2 * pp][1], o[2 * pp][2], o[2 * pp][3],
                        a0, a1, a2, a3, r0, r1);
                mma_f16(o[2 * pp + 1][0], o[2 * pp + 1][1], o[2 * pp + 1][2], o[2 * pp + 1][3],
                        a0, a1, a2, a3, r2, r3);
            }
            mma_f16(o[16][0], o[16][1], o[16][2], o[16][3],
                    a0, a1, a2, a3, ones_b, ones_b);
        }

        __syncthreads();
        if (kb + 2 < NKT) load_kv(kb + 2);
    }

    const int src = lane & ~3;
    const float l0 = __shfl_sync(0xffffffffu, o[16][0], src);
    const float l1 = __shfl_sync(0xffffffffu, o[16][2], src);
    const float inv0 = 1.f / l0;
    const float inv1 = 1.f / l1;

    const int gr0 = b * KSEQ + q0 + wid * 16 + (lane >> 2);
    const int col0 = h * KHD + 2 * (lane & 3);
#pragma unroll
    for (int t = 0; t < 16; t++) {
#pragma unroll
        for (int rr = 0; rr < 2; rr++) {
            float v0 = o[t][2 * rr + 0] * (rr ? inv1 : inv0);
            float v1 = o[t][2 * rr + 1] * (rr ? inv1 : inv0);
            __nv_bfloat16 h0 = __float2bfloat16(v0);
            __nv_bfloat16 h1 = __float2bfloat16(v1);
            __nv_bfloat16 l0b = __float2bfloat16(v0 - __bfloat162float(h0));
            __nv_bfloat16 l1b = __float2bfloat16(v1 - __bfloat162float(h1));
            uint32_t hp = (uint32_t)__bfloat16_as_ushort(h0)
                        | ((uint32_t)__bfloat16_as_ushort(h1) << 16);
            uint32_t lp = (uint32_t)__bfloat16_as_ushort(l0b)
                        | ((uint32_t)__bfloat16_as_ushort(l1b) << 16);
            __nv_bfloat16* dst = g_combbig + (size_t)(gr0 + rr * 8) * KBIG + col0 + t * 8;
            *(uint32_t*)(dst)            = hp;
            *(uint32_t*)(dst + KDIM)     = lp;
            *(uint32_t*)(dst + 2 * KDIM) = hp;
        }
    }
}

// ---------------------------------------------------------------------------
extern "C" void kernel_launch(void* const* d_in, const int* in_sizes, int n_in,
                              void* d_out, int out_size)
{
    (void)in_sizes; (void)n_in; (void)out_size;
    const float* x     = (const float*)d_in[0];
    const float* w_qkv = (const float*)d_in[1];
    const float* w_out = (const float*)d_in[2];
    float* out = (float*)d_out;

    __half* qkv16_p;     cudaGetSymbolAddress((void**)&qkv16_p, g_qkv16);
    __half* x16_p;       cudaGetSymbolAddress((void**)&x16_p,   g_x16);
    __half* wq16_p;      cudaGetSymbolAddress((void**)&wq16_p,  g_wq16);
    __nv_bfloat16* cb_p; cudaGetSymbolAddress((void**)&cb_p,    g_combbig);
    __nv_bfloat16* wo_p; cudaGetSymbolAddress((void**)&wo_p,    g_woutbig);

    // 0) Converts / splits
    {
        int t4;
        t4 = KROWS * KDIM / 4;
        conv_f16<<<(t4 + 255) / 256, 256>>>(x, x16_p, t4);
        t4 = KQKV * KDIM / 4;
        conv_f16<<<(t4 + 255) / 256, 256>>>(w_qkv, wq16_p, t4);
        t4 = KMODEL * KDIM / 4;
        split_bf16<<<(t4 + 255) / 256, 256>>>(w_out, wo_p, t4, KDIM);
    }

    cudaFuncSetAttribute(gemm_hmma<true>,
                         cudaFuncAttributeMaxDynamicSharedMemorySize, GEMM_SMEM);
    cudaFuncSetAttribute(gemm_hmma<false>,
                         cudaFuncAttributeMaxDynamicSharedMemorySize, GEMM_SMEM);

    // 1) QKV projection (fp16 HMMA, K=2048) -> fp16 g_qkv16
    {
        dim3 grid(KQKV / BN, KROWS / BM);
        gemm_hmma<true><<<grid, 256, GEMM_SMEM>>>(
            (const uint16_t*)x16_p, (const uint16_t*)wq16_p,
            nullptr, qkv16_p, KQKV, KDIM);
    }

    // 2) Flash attention (fp16 HMMA) -> split-bf16 g_combbig
    {
        cudaFuncSetAttribute(flash_f16,
                             cudaFuncAttributeMaxDynamicSharedMemorySize, FLASH_SMEM);
        dim3 grid(KSEQ / FBQ, KNH, KBATCH);
        flash_f16<<<grid, 128, FLASH_SMEM>>>();
    }

    // 3) Output projection (bf16 3-term split, K=6144) -> fp32 out
    {
        dim3 grid(KMODEL / BN, KROWS / BM);
        gemm_hmma<false><<<grid, 256, GEMM_SMEM>>>(
            (const uint16_t*)cb_p, (const uint16_t*)wo_p,
            out, nullptr, KMODEL, KBIG);
    }
}

// round 14
// speedup vs baseline: 7.4517x; 1.0287x over previous
#include <cuda_runtime.h>
#include <cuda_bf16.h>
#include <cuda_fp16.h>
#include <math.h>
#include <stdint.h>

// Problem constants
#define KDIM   2048
#define KHD    128
#define KNH    16
#define KBATCH 2
#define KSEQ   2048
#define KQKV   6144
#define KMODEL 2048
#define KROWS  (KBATCH * KSEQ)   // 4096
#define KBIG   (3 * KDIM)        // 6144 : split-K encoding for out-proj

// Scratch (device globals: allocation-free rule)
__device__ __align__(16) __half g_qkv16[(size_t)KROWS * KQKV];          // fp16 qkv for flash
__device__ __align__(16) __half g_x16[(size_t)KROWS * KDIM];            // fp16 x
__device__ __align__(16) __half g_wq16[(size_t)KQKV * KDIM];            // fp16 w_qkv
__device__ __align__(16) __nv_bfloat16 g_combbig[(size_t)KROWS * KBIG]; // A-side split of attn out
__device__ __align__(16) __nv_bfloat16 g_woutbig[(size_t)KMODEL * KBIG];// B-side split of w_out

// ---------------------------------------------------------------------------
// fp32 -> fp16 convert (contiguous)
// ---------------------------------------------------------------------------
__global__ __launch_bounds__(256) void conv_f16(
    const float* __restrict__ src, __half* __restrict__ dst, int total4)
{
    int idx = blockIdx.x * blockDim.x + threadIdx.x;
    if (idx >= total4) return;
    float4 v = *(const float4*)(src + (size_t)idx * 4);
    __half2 h0 = __floats2half2_rn(v.x, v.y);
    __half2 h1 = __floats2half2_rn(v.z, v.w);
    uint2 p;
    p.x = *(uint32_t*)&h0;
    p.y = *(uint32_t*)&h1;
    *(uint2*)(dst + (size_t)idx * 4) = p;
}

// ---------------------------------------------------------------------------
// Split fp32 -> bf16 hi/lo, K-concatenated (B operand: [hi | hi | lo]).
// ---------------------------------------------------------------------------
__global__ __launch_bounds__(256) void split_bf16(
    const float* __restrict__ src, __nv_bfloat16* __restrict__ dst,
    int total4, int K)
{
    int idx = blockIdx.x * blockDim.x + threadIdx.x;
    if (idx >= total4) return;
    int e = idx * 4;
    int r = e / K;
    int k = e - r * K;
    float4 v = *(const float4*)(src + (size_t)e);
    float a[4] = {v.x, v.y, v.z, v.w};
    unsigned short hs[4], ls[4];
#pragma unroll
    for (int i = 0; i < 4; i++) {
        __nv_bfloat16 h = __float2bfloat16(a[i]);
        hs[i] = __bfloat16_as_ushort(h);
        ls[i] = __bfloat16_as_ushort(__float2bfloat16(a[i] - __bfloat162float(h)));
    }
    uint2 hp, lp;
    hp.x = (uint32_t)hs[0] | ((uint32_t)hs[1] << 16);
    hp.y = (uint32_t)hs[2] | ((uint32_t)hs[3] << 16);
    lp.x = (uint32_t)ls[0] | ((uint32_t)ls[1] << 16);
    lp.y = (uint32_t)ls[2] | ((uint32_t)ls[3] << 16);
    size_t rb = (size_t)r * (3 * K) + k;
    *(uint2*)(dst + rb)         = hp;
    *(uint2*)(dst + rb + K)     = hp;
    *(uint2*)(dst + rb + 2 * K) = lp;
}

// ---------------------------------------------------------------------------
// Common helpers
// ---------------------------------------------------------------------------
__device__ __forceinline__ uint32_t smem_u32(const void* p) {
    uint32_t a;
    asm("{ .reg .u64 t; cvta.to.shared.u64 t, %1; cvt.u32.u64 %0, t; }"
        : "=r"(a) : "l"(p));
    return a;
}
__device__ __forceinline__ uint32_t sw128(uint32_t o) { return o ^ ((o >> 3) & 0x70); }

__device__ __forceinline__ void ldsm_x4(uint32_t addr, uint32_t& r0, uint32_t& r1,
                                        uint32_t& r2, uint32_t& r3) {
    asm volatile("ldmatrix.sync.aligned.m8n8.x4.shared.b16 {%0,%1,%2,%3}, [%4];"
                 : "=r"(r0), "=r"(r1), "=r"(r2), "=r"(r3) : "r"(addr));
}
__device__ __forceinline__ void ldsm_x4t(uint32_t addr, uint32_t& r0, uint32_t& r1,
                                         uint32_t& r2, uint32_t& r3) {
    asm volatile("ldmatrix.sync.aligned.m8n8.x4.trans.shared.b16 {%0,%1,%2,%3}, [%4];"
                 : "=r"(r0), "=r"(r1), "=r"(r2), "=r"(r3) : "r"(addr));
}

__device__ __forceinline__ void mma_bf16(float& c0, float& c1, float& c2, float& c3,
                                         uint32_t a0, uint32_t a1, uint32_t a2, uint32_t a3,
                                         uint32_t b0, uint32_t b1) {
    asm volatile(
        "mma.sync.aligned.m16n8k16.row.col.f32.bf16.bf16.f32 "
        "{%0,%1,%2,%3}, {%4,%5,%6,%7}, {%8,%9}, {%0,%1,%2,%3};"
        : "+f"(c0), "+f"(c1), "+f"(c2), "+f"(c3)
        : "r"(a0), "r"(a1), "r"(a2), "r"(a3), "r"(b0), "r"(b1));
}
__device__ __forceinline__ void mma_f16(float& c0, float& c1, float& c2, float& c3,
                                        uint32_t a0, uint32_t a1, uint32_t a2, uint32_t a3,
                                        uint32_t b0, uint32_t b1) {
    asm volatile(
        "mma.sync.aligned.m16n8k16.row.col.f32.f16.f16.f32 "
        "{%0,%1,%2,%3}, {%4,%5,%6,%7}, {%8,%9}, {%0,%1,%2,%3};"
        : "+f"(c0), "+f"(c1), "+f"(c2), "+f"(c3)
        : "r"(a0), "r"(a1), "r"(a2), "r"(a3), "r"(b0), "r"(b1));
}
__device__ __forceinline__ float ex2f(float x) {
    float y;
    asm("ex2.approx.ftz.f32 %0, %1;" : "=f"(y) : "f"(x));
    return y;
}
#define CPA16(dst, src) \
    asm volatile("cp.async.cg.shared.global [%0], [%1], 16;" :: "r"(dst), "l"(src) : "memory")

// ---------------------------------------------------------------------------
// HMMA GEMM: C = A[M,K] * B[N,K]^T, 16-bit operands (fp16 or bf16).
// CTA 128x128, BK=64, 3-stage cp.async multistage (single __syncthreads per
// chunk), SW128 swizzled smem, m16n8k16. Output fp32 (Cf) or fp16 (Ch).
// ---------------------------------------------------------------------------
#define BM 128
#define BN 128
#define BK 64
#define TILE_BYTES 16384
#define STAGE_BYTES 32768
#define NSTAGE 3
#define GEMM_SMEM   (NSTAGE * STAGE_BYTES)   // 98304

template <bool USE_F16>
__global__ __launch_bounds__(256, 2) void gemm_hmma(
    const uint16_t* __restrict__ A, const uint16_t* __restrict__ B,
    float* __restrict__ Cf, __half* __restrict__ Ch, int N, int K)
{
    extern __shared__ char smem[];
    const uint32_t sbase = smem_u32(smem);
    const int tid = threadIdx.x;
    const int wid = tid >> 5;
    const int lane = tid & 31;
    const int wm = wid >> 1;
    const int wn = wid & 1;
    const int bm = blockIdx.y * BM;
    const int bn = blockIdx.x * BN;
    const int nchunk = K / BK;
    const size_t rowB = (size_t)K * 2;

    auto load_chunk = [&](int c, int stage) {
        const uint32_t st = (uint32_t)stage * STAGE_BYTES;
        const char* Asrc = (const char*)(A + (size_t)bm * K) + (size_t)c * 128;
        const char* Bsrc = (const char*)(B + (size_t)bn * K) + (size_t)c * 128;
#pragma unroll
        for (int i = 0; i < 4; i++) {
            int u = i * 256 + tid;
            int row = u >> 3, ku = u & 7;
            uint32_t dst = sbase + st + sw128((uint32_t)(row * 128 + ku * 16));
            CPA16(dst, Asrc + (size_t)row * rowB + ku * 16);
        }
#pragma unroll
        for (int i = 0; i < 4; i++) {
            int u = i * 256 + tid;
            int row = u >> 3, ku = u & 7;
            uint32_t dst = sbase + st + TILE_BYTES + sw128((uint32_t)(row * 128 + ku * 16));
            CPA16(dst, Bsrc + (size_t)row * rowB + ku * 16);
        }
        asm volatile("cp.async.commit_group;" ::: "memory");
    };

    float acc[2][8][4];
#pragma unroll
    for (int mt = 0; mt < 2; mt++)
#pragma unroll
        for (int nt = 0; nt < 8; nt++)
#pragma unroll
            for (int q = 0; q < 4; q++) acc[mt][nt][q] = 0.f;

    load_chunk(0, 0);
    load_chunk(1, 1);

    const int lrow = lane & 15;
    const int lsel = lane >> 4;
    int s_cur = 0;      // stage of chunk c
    int s_nxt = 2;      // stage for chunk c+2

#pragma unroll 1
    for (int c = 0; c < nchunk; c++) {
        if (c + 1 < nchunk) { asm volatile("cp.async.wait_group 1;" ::: "memory"); }
        else                { asm volatile("cp.async.wait_group 0;" ::: "memory"); }
        __syncthreads();

        // Prefetch chunk c+2 into the buffer compute(c-1) just vacated.
        if (c + 2 < nchunk) load_chunk(c + 2, s_nxt);

        const uint32_t ab = sbase + (uint32_t)s_cur * STAGE_BYTES;
        const uint32_t bb = ab + TILE_BYTES;
        const int m0 = wm * 32;
        const int n0 = wn * 64;

#pragma unroll
        for (int ks = 0; ks < 4; ks++) {
            const int chk = 2 * ks + lsel;
            uint32_t a[2][4];
#pragma unroll
            for (int mt = 0; mt < 2; mt++) {
                int r = m0 + mt * 16 + lrow;
                ldsm_x4(ab + sw128((uint32_t)(r * 128 + chk * 16)),
                        a[mt][0], a[mt][1], a[mt][2], a[mt][3]);
            }
            uint32_t blo[8], bhi[8];
#pragma unroll
            for (int p = 0; p < 4; p++) {
                int r = n0 + p * 16 + lrow;
                uint32_t r0, r1, r2, r3;
                ldsm_x4(bb + sw128((uint32_t)(r * 128 + chk * 16)), r0, r1, r2, r3);
                blo[2 * p] = r0; blo[2 * p + 1] = r1;
                bhi[2 * p] = r2; bhi[2 * p + 1] = r3;
            }
#pragma unroll
            for (int mt = 0; mt < 2; mt++)
#pragma unroll
                for (int nt = 0; nt < 8; nt++) {
                    if (USE_F16)
                        mma_f16(acc[mt][nt][0], acc[mt][nt][1], acc[mt][nt][2], acc[mt][nt][3],
                                a[mt][0], a[mt][1], a[mt][2], a[mt][3], blo[nt], bhi[nt]);
                    else
                        mma_bf16(acc[mt][nt][0], acc[mt][nt][1], acc[mt][nt][2], acc[mt][nt][3],
                                 a[mt][0], a[mt][1], a[mt][2], a[mt][3], blo[nt], bhi[nt]);
                }
        }

        s_cur = (s_cur == NSTAGE - 1) ? 0 : s_cur + 1;
        s_nxt = (s_nxt == NSTAGE - 1) ? 0 : s_nxt + 1;
    }

    const int mbase = bm + wm * 32 + (lane >> 2);
    const int nbase = bn + wn * 64 + 2 * (lane & 3);
    if (Ch) {
#pragma unroll
        for (int mt = 0; mt < 2; mt++)
#pragma unroll
            for (int nt = 0; nt < 8; nt++) {
                __half* p0 = Ch + (size_t)(mbase + mt * 16) * N + nbase + nt * 8;
                __half* p1 = Ch + (size_t)(mbase + mt * 16 + 8) * N + nbase + nt * 8;
                *(__half2*)p0 = __floats2half2_rn(acc[mt][nt][0], acc[mt][nt][1]);
                *(__half2*)p1 = __floats2half2_rn(acc[mt][nt][2], acc[mt][nt][3]);
            }
    } else {
#pragma unroll
        for (int mt = 0; mt < 2; mt++)
#pragma unroll
            for (int nt = 0; nt < 8; nt++) {
                float* p0 = Cf + (size_t)(mbase + mt * 16) * N + nbase + nt * 8;
                float* p1 = Cf + (size_t)(mbase + mt * 16 + 8) * N + nbase + nt * 8;
                *(float2*)p0 = make_float2(acc[mt][nt][0], acc[mt][nt][1]);
                *(float2*)p1 = make_float2(acc[mt][nt][2], acc[mt][nt][3]);
            }
    }
}

// ---------------------------------------------------------------------------
// Flash attention, fp16 HMMA + f16x2 exp2, online softmax.
// Grid (S/64, H, B), 128 threads = 4 warps, warp = 16 q rows.
// ---------------------------------------------------------------------------
#define FBQ 64
#define FBK 64
#define NKT (KSEQ / FBK)         // 32
#define FQ_OFF 0
#define FK_OFF 16384
#define FV_OFF 49152
#define FLASH_SMEM 81920

__global__ __launch_bounds__(128) void flash_f16()
{
    extern __shared__ char smem[];
    const uint32_t sbase = smem_u32(smem);
    const int tid = threadIdx.x;
    const int wid = tid >> 5;
    const int lane = tid & 31;
    const int qb = blockIdx.x;
    const int h  = blockIdx.y;
    const int b  = blockIdx.z;
    const int q0 = qb * FBQ;

    const char* qkvb = (const char*)g_qkv16;
    const size_t rowB = (size_t)KQKV * 2;

    {
        const size_t base = (size_t)(b * KSEQ + q0) * rowB + (size_t)h * 256;
#pragma unroll
        for (int i = 0; i < 8; i++) {
            int u = i * 128 + tid;
            int row = u >> 4, c16 = u & 15;
            uint32_t dst = sbase + FQ_OFF + (uint32_t)(c16 >> 3) * 8192
                         + sw128((uint32_t)(row * 128 + (c16 & 7) * 16));
            CPA16(dst, qkvb + base + (size_t)row * rowB + c16 * 16);
        }
    }
    auto load_kv = [&](int kb) {
        const uint32_t st = (uint32_t)(kb & 1) * 16384;
        const size_t kbase = (size_t)(b * KSEQ + kb * FBK) * rowB + (size_t)(KNH + h) * 256;
        const size_t vbase = (size_t)(b * KSEQ + kb * FBK) * rowB + (size_t)(2 * KNH + h) * 256;
#pragma unroll
        for (int i = 0; i < 8; i++) {
            int u = i * 128 + tid;
            int row = u >> 4, c16 = u & 15;
            uint32_t off = (uint32_t)(c16 >> 3) * 8192
                         + sw128((uint32_t)(row * 128 + (c16 & 7) * 16));
            CPA16(sbase + FK_OFF + st + off, qkvb + kbase + (size_t)row * rowB + c16 * 16);
        }
#pragma unroll
        for (int i = 0; i < 8; i++) {
            int u = i * 128 + tid;
            int row = u >> 4, c16 = u & 15;
            uint32_t off = (uint32_t)(c16 >> 3) * 8192
                         + sw128((uint32_t)(row * 128 + (c16 & 7) * 16));
            CPA16(sbase + FV_OFF + st + off, qkvb + vbase + (size_t)row * rowB + c16 * 16);
        }
        asm volatile("cp.async.commit_group;" ::: "memory");
    };

    load_kv(0);
    load_kv(1);

    float o[17][4];
#pragma unroll
    for (int t = 0; t < 17; t++)
#pragma unroll
        for (int q = 0; q < 4; q++) o[t][q] = 0.f;
    float m0 = -1e30f, m1 = -1e30f;

    const float sl2e = 1.4426950408889634f * 0.08838834764831845f;
    const int lrow = lane & 15;
    const int lsel = lane >> 4;
    const uint32_t ones_b = (lane < 4) ? 0x3C003C00u : 0u;

#pragma unroll 1
    for (int kb = 0; kb < NKT; kb++) {
        if (kb + 1 < NKT) { asm volatile("cp.async.wait_group 1;" ::: "memory"); }
        else              { asm volatile("cp.async.wait_group 0;" ::: "memory"); }
        __syncthreads();

        const uint32_t kbuf = sbase + FK_OFF + (uint32_t)(kb & 1) * 16384;
        const uint32_t vbuf = sbase + FV_OFF + (uint32_t)(kb & 1) * 16384;
        const uint32_t qbuf = sbase + FQ_OFF;

        float s[8][4];
#pragma unroll
        for (int nt = 0; nt < 8; nt++)
#pragma unroll
            for (int q = 0; q < 4; q++) s[nt][q] = 0.f;

#pragma unroll
        for (int ks = 0; ks < 8; ks++) {
            const uint32_t chko = (uint32_t)(ks >> 2) * 8192;
            const int chk = 2 * (ks & 3) + lsel;
            uint32_t a0, a1, a2, a3;
            {
                int r = wid * 16 + lrow;
                ldsm_x4(qbuf + chko + sw128((uint32_t)(r * 128 + chk * 16)), a0, a1, a2, a3);
            }
            uint32_t blo[8], bhi[8];
#pragma unroll
            for (int p = 0; p < 4; p++) {
                int r = p * 16 + lrow;
                uint32_t r0, r1, r2, r3;
                ldsm_x4(kbuf + chko + sw128((uint32_t)(r * 128 + chk * 16)), r0, r1, r2, r3);
                blo[2 * p] = r0; blo[2 * p + 1] = r1;
                bhi[2 * p] = r2; bhi[2 * p + 1] = r3;
            }
#pragma unroll
            for (int nt = 0; nt < 8; nt++)
                mma_f16(s[nt][0], s[nt][1], s[nt][2], s[nt][3],
                        a0, a1, a2, a3, blo[nt], bhi[nt]);
        }

        float mx0 = -1e30f, mx1 = -1e30f;
#pragma unroll
        for (int nt = 0; nt < 8; nt++) {
            s[nt][0] *= sl2e; s[nt][1] *= sl2e;
            s[nt][2] *= sl2e; s[nt][3] *= sl2e;
            mx0 = fmaxf(mx0, fmaxf(s[nt][0], s[nt][1]));
            mx1 = fmaxf(mx1, fmaxf(s[nt][2], s[nt][3]));
        }
        mx0 = fmaxf(mx0, __shfl_xor_sync(0xffffffffu, mx0, 1));
        mx0 = fmaxf(mx0, __shfl_xor_sync(0xffffffffu, mx0, 2));
        mx1 = fmaxf(mx1, __shfl_xor_sync(0xffffffffu, mx1, 1));
        mx1 = fmaxf(mx1, __shfl_xor_sync(0xffffffffu, mx1, 2));
        const float mn0 = fmaxf(m0, mx0);
        const float mn1 = fmaxf(m1, mx1);
        const float corr0 = ex2f(m0 - mn0);
        const float corr1 = ex2f(m1 - mn1);
        m0 = mn0; m1 = mn1;
#pragma unroll
        for (int t = 0; t < 17; t++) {
            o[t][0] *= corr0; o[t][1] *= corr0;
            o[t][2] *= corr1; o[t][3] *= corr1;
        }
        uint32_t p01[8], p23[8];
#pragma unroll
        for (int nt = 0; nt < 8; nt++) {
            __half2 h0 = h2exp2(__floats2half2_rn(s[nt][0] - mn0, s[nt][1] - mn0));
            __half2 h1 = h2exp2(__floats2half2_rn(s[nt][2] - mn1, s[nt][3] - mn1));
            p01[nt] = *(uint32_t*)&h0;
            p23[nt] = *(uint32_t*)&h1;
        }

        const int grp  = lane >> 3;
        const int glr  = lane & 7;
#pragma unroll
        for (int ks = 0; ks < 4; ks++) {
            const uint32_t a0 = p01[2 * ks],     a1 = p23[2 * ks];
            const uint32_t a2 = p01[2 * ks + 1], a3 = p23[2 * ks + 1];
            const int key = 16 * ks + (grp & 1) * 8 + glr;
#pragma unroll
            for (int pp = 0; pp < 8; pp++) {
                const int d = pp * 16 + (grp >> 1) * 8;
                const uint32_t addr = vbuf + (uint32_t)(d >> 6) * 8192
                                    + sw128((uint32_t)(key * 128 + (d & 63) * 2));
                uint32_t r0, r1, r2, r3;
                ldsm_x4t(addr, r0, r1, r2, r3);
                mma_f16(o[2 * pp][0], o[2 * pp][1], o[2 * pp][2], o[2 * pp][3],
                        a0, a1, a2, a3, r0, r1);
                mma_f16(o[2 * pp + 1][0], o[2 * pp + 1][1], o[2 * pp + 1][2], o[2 * pp + 1][3],
                        a0, a1, a2, a3, r2, r3);
            }
            mma_f16(o[16][0], o[16][1], o[16][2], o[16][3],
                    a0, a1, a2, a3, ones_b, ones_b);
        }

        __syncthreads();
        if (kb + 2 < NKT) load_kv(kb + 2);
    }

    const int src = lane & ~3;
    const float l0 = __shfl_sync(0xffffffffu, o[16][0], src);
    const float l1 = __shfl_sync(0xffffffffu, o[16][2], src);
    const float inv0 = 1.f / l0;
    const float inv1 = 1.f / l1;

    const int gr0 = b * KSEQ + q0 + wid * 16 + (lane >> 2);
    const int col0 = h * KHD + 2 * (lane & 3);
#pragma unroll
    for (int t = 0; t < 16; t++) {
#pragma unroll
        for (int rr = 0; rr < 2; rr++) {
            float v0 = o[t][2 * rr + 0] * (rr ? inv1 : inv0);
            float v1 = o[t][2 * rr + 1] * (rr ? inv1 : inv0);
            __nv_bfloat16 h0 = __float2bfloat16(v0);
            __nv_bfloat16 h1 = __float2bfloat16(v1);
            __nv_bfloat16 l0b = __float2bfloat16(v0 - __bfloat162float(h0));
            __nv_bfloat16 l1b = __float2bfloat16(v1 - __bfloat162float(h1));
            uint32_t hp = (uint32_t)__bfloat16_as_ushort(h0)
                        | ((uint32_t)__bfloat16_as_ushort(h1) << 16);
            uint32_t lp = (uint32_t)__bfloat16_as_ushort(l0b)
                        | ((uint32_t)__bfloat16_as_ushort(l1b) << 16);
            __nv_bfloat16* dst = g_combbig + (size_t)(gr0 + rr * 8) * KBIG + col0 + t * 8;
            *(uint32_t*)(dst)            = hp;
            *(uint32_t*)(dst + KDIM)     = lp;
            *(uint32_t*)(dst + 2 * KDIM) = hp;
        }
    }
}

// ---------------------------------------------------------------------------
extern "C" void kernel_launch(void* const* d_in, const int* in_sizes, int n_in,
                              void* d_out, int out_size)
{
    (void)in_sizes; (void)n_in; (void)out_size;
    const float* x     = (const float*)d_in[0];
    const float* w_qkv = (const float*)d_in[1];
    const float* w_out = (const float*)d_in[2];
    float* out = (float*)d_out;

    __half* qkv16_p;     cudaGetSymbolAddress((void**)&qkv16_p, g_qkv16);
    __half* x16_p;       cudaGetSymbolAddress((void**)&x16_p,   g_x16);
    __half* wq16_p;      cudaGetSymbolAddress((void**)&wq16_p,  g_wq16);
    __nv_bfloat16* cb_p; cudaGetSymbolAddress((void**)&cb_p,    g_combbig);
    __nv_bfloat16* wo_p; cudaGetSymbolAddress((void**)&wo_p,    g_woutbig);

    // 0) Converts / splits
    {
        int t4;
        t4 = KROWS * KDIM / 4;
        conv_f16<<<(t4 + 255) / 256, 256>>>(x, x16_p, t4);
        t4 = KQKV * KDIM / 4;
        conv_f16<<<(t4 + 255) / 256, 256>>>(w_qkv, wq16_p, t4);
        t4 = KMODEL * KDIM / 4;
        split_bf16<<<(t4 + 255) / 256, 256>>>(w_out, wo_p, t4, KDIM);
    }

    cudaFuncSetAttribute(gemm_hmma<true>,
                         cudaFuncAttributeMaxDynamicSharedMemorySize, GEMM_SMEM);
    cudaFuncSetAttribute(gemm_hmma<false>,
                         cudaFuncAttributeMaxDynamicSharedMemorySize, GEMM_SMEM);

    // 1) QKV projection (fp16 HMMA, K=2048) -> fp16 g_qkv16
    {
        dim3 grid(KQKV / BN, KROWS / BM);
        gemm_hmma<true><<<grid, 256, GEMM_SMEM>>>(
            (const uint16_t*)x16_p, (const uint16_t*)wq16_p,
            nullptr, qkv16_p, KQKV, KDIM);
    }

    // 2) Flash attention (fp16 HMMA) -> split-bf16 g_combbig
    {
        cudaFuncSetAttribute(flash_f16,
                             cudaFuncAttributeMaxDynamicSharedMemorySize, FLASH_SMEM);
        dim3 grid(KSEQ / FBQ, KNH, KBATCH);
        flash_f16<<<grid, 128, FLASH_SMEM>>>();
    }

    // 3) Output projection (bf16 3-term split, K=6144) -> fp32 out
    {
        dim3 grid(KMODEL / BN, KROWS / BM);
        gemm_hmma<false><<<grid, 256, GEMM_SMEM>>>(
            (const uint16_t*)cb_p, (const uint16_t*)wo_p,
            out, nullptr, KMODEL, KBIG);
    }
}

// round 15
// speedup vs baseline: 7.9670x; 1.0692x over previous
#include <cuda_runtime.h>
#include <cuda_bf16.h>
#include <cuda_fp16.h>
#include <math.h>
#include <stdint.h>

// Problem constants
#define KDIM   2048
#define KHD    128
#define KNH    16
#define KBATCH 2
#define KSEQ   2048
#define KQKV   6144
#define KMODEL 2048
#define KROWS  (KBATCH * KSEQ)   // 4096
#define K2     (2 * KDIM)        // 4096 : [hi | lo] / [hi | hi] fp16 split-K

// Scratch (device globals: allocation-free rule)
__device__ __align__(16) __half g_qkv16[(size_t)KROWS * KQKV];     // fp16 qkv for flash
__device__ __align__(16) __half g_x16[(size_t)KROWS * KDIM];       // fp16 x
__device__ __align__(16) __half g_wq16[(size_t)KQKV * KDIM];       // fp16 w_qkv
__device__ __align__(16) __half g_comb2[(size_t)KROWS * K2];       // [hi|lo] attn out
__device__ __align__(16) __half g_wout2[(size_t)KMODEL * K2];      // [hi|hi] w_out

// ---------------------------------------------------------------------------
// fp32 -> fp16 convert (contiguous)
// ---------------------------------------------------------------------------
__global__ __launch_bounds__(256) void conv_f16(
    const float* __restrict__ src, __half* __restrict__ dst, int total4)
{
    int idx = blockIdx.x * blockDim.x + threadIdx.x;
    if (idx >= total4) return;
    float4 v = *(const float4*)(src + (size_t)idx * 4);
    __half2 h0 = __floats2half2_rn(v.x, v.y);
    __half2 h1 = __floats2half2_rn(v.z, v.w);
    uint2 p;
    p.x = *(uint32_t*)&h0;
    p.y = *(uint32_t*)&h1;
    *(uint2*)(dst + (size_t)idx * 4) = p;
}

// ---------------------------------------------------------------------------
// fp32 -> fp16 duplicated K-concat: dst row = [h | h]  (B operand)
// ---------------------------------------------------------------------------
__global__ __launch_bounds__(256) void dup_f16(
    const float* __restrict__ src, __half* __restrict__ dst, int total4, int K)
{
    int idx = blockIdx.x * blockDim.x + threadIdx.x;
    if (idx >= total4) return;
    int e = idx * 4;
    int r = e / K;
    int k = e - r * K;
    float4 v = *(const float4*)(src + (size_t)e);
    __half2 h0 = __floats2half2_rn(v.x, v.y);
    __half2 h1 = __floats2half2_rn(v.z, v.w);
    uint2 p;
    p.x = *(uint32_t*)&h0;
    p.y = *(uint32_t*)&h1;
    size_t rb = (size_t)r * (2 * K) + k;
    *(uint2*)(dst + rb)     = p;
    *(uint2*)(dst + rb + K) = p;
}

// ---------------------------------------------------------------------------
// Common helpers
// ---------------------------------------------------------------------------
__device__ __forceinline__ uint32_t smem_u32(const void* p) {
    uint32_t a;
    asm("{ .reg .u64 t; cvta.to.shared.u64 t, %1; cvt.u32.u64 %0, t; }"
        : "=r"(a) : "l"(p));
    return a;
}
__device__ __forceinline__ uint32_t sw128(uint32_t o) { return o ^ ((o >> 3) & 0x70); }

__device__ __forceinline__ void ldsm_x4(uint32_t addr, uint32_t& r0, uint32_t& r1,
                                        uint32_t& r2, uint32_t& r3) {
    asm volatile("ldmatrix.sync.aligned.m8n8.x4.shared.b16 {%0,%1,%2,%3}, [%4];"
                 : "=r"(r0), "=r"(r1), "=r"(r2), "=r"(r3) : "r"(addr));
}
__device__ __forceinline__ void ldsm_x4t(uint32_t addr, uint32_t& r0, uint32_t& r1,
                                         uint32_t& r2, uint32_t& r3) {
    asm volatile("ldmatrix.sync.aligned.m8n8.x4.trans.shared.b16 {%0,%1,%2,%3}, [%4];"
                 : "=r"(r0), "=r"(r1), "=r"(r2), "=r"(r3) : "r"(addr));
}
__device__ __forceinline__ void mma_f16(float& c0, float& c1, float& c2, float& c3,
                                        uint32_t a0, uint32_t a1, uint32_t a2, uint32_t a3,
                                        uint32_t b0, uint32_t b1) {
    asm volatile(
        "mma.sync.aligned.m16n8k16.row.col.f32.f16.f16.f32 "
        "{%0,%1,%2,%3}, {%4,%5,%6,%7}, {%8,%9}, {%0,%1,%2,%3};"
        : "+f"(c0), "+f"(c1), "+f"(c2), "+f"(c3)
        : "r"(a0), "r"(a1), "r"(a2), "r"(a3), "r"(b0), "r"(b1));
}
__device__ __forceinline__ float ex2f(float x) {
    float y;
    asm("ex2.approx.ftz.f32 %0, %1;" : "=f"(y) : "f"(x));
    return y;
}
#define CPA16(dst, src) \
    asm volatile("cp.async.cg.shared.global [%0], [%1], 16;" :: "r"(dst), "l"(src) : "memory")

// ---------------------------------------------------------------------------
// HMMA fp16 GEMM: C = A[M,K] * B[N,K]^T.
// CTA 128x128, BK=64, 3-stage cp.async multistage, SW128 smem, m16n8k16.
// Output fp32 (Cf) or fp16 (Ch).
// ---------------------------------------------------------------------------
#define BM 128
#define BN 128
#define BK 64
#define TILE_BYTES 16384
#define STAGE_BYTES 32768
#define NSTAGE 3
#define GEMM_SMEM   (NSTAGE * STAGE_BYTES)   // 98304

__global__ __launch_bounds__(256, 2) void gemm_hmma(
    const uint16_t* __restrict__ A, const uint16_t* __restrict__ B,
    float* __restrict__ Cf, __half* __restrict__ Ch, int N, int K)
{
    extern __shared__ char smem[];
    const uint32_t sbase = smem_u32(smem);
    const int tid = threadIdx.x;
    const int wid = tid >> 5;
    const int lane = tid & 31;
    const int wm = wid >> 1;
    const int wn = wid & 1;
    const int bm = blockIdx.y * BM;
    const int bn = blockIdx.x * BN;
    const int nchunk = K / BK;
    const size_t rowB = (size_t)K * 2;

    auto load_chunk = [&](int c, int stage) {
        const uint32_t st = (uint32_t)stage * STAGE_BYTES;
        const char* Asrc = (const char*)(A + (size_t)bm * K) + (size_t)c * 128;
        const char* Bsrc = (const char*)(B + (size_t)bn * K) + (size_t)c * 128;
#pragma unroll
        for (int i = 0; i < 4; i++) {
            int u = i * 256 + tid;
            int row = u >> 3, ku = u & 7;
            uint32_t dst = sbase + st + sw128((uint32_t)(row * 128 + ku * 16));
            CPA16(dst, Asrc + (size_t)row * rowB + ku * 16);
        }
#pragma unroll
        for (int i = 0; i < 4; i++) {
            int u = i * 256 + tid;
            int row = u >> 3, ku = u & 7;
            uint32_t dst = sbase + st + TILE_BYTES + sw128((uint32_t)(row * 128 + ku * 16));
            CPA16(dst, Bsrc + (size_t)row * rowB + ku * 16);
        }
        asm volatile("cp.async.commit_group;" ::: "memory");
    };

    float acc[2][8][4];
#pragma unroll
    for (int mt = 0; mt < 2; mt++)
#pragma unroll
        for (int nt = 0; nt < 8; nt++)
#pragma unroll
            for (int q = 0; q < 4; q++) acc[mt][nt][q] = 0.f;

    load_chunk(0, 0);
    load_chunk(1, 1);

    const int lrow = lane & 15;
    const int lsel = lane >> 4;
    int s_cur = 0;
    int s_nxt = 2;

#pragma unroll 1
    for (int c = 0; c < nchunk; c++) {
        if (c + 1 < nchunk) { asm volatile("cp.async.wait_group 1;" ::: "memory"); }
        else                { asm volatile("cp.async.wait_group 0;" ::: "memory"); }
        __syncthreads();

        if (c + 2 < nchunk) load_chunk(c + 2, s_nxt);

        const uint32_t ab = sbase + (uint32_t)s_cur * STAGE_BYTES;
        const uint32_t bb = ab + TILE_BYTES;
        const int m0 = wm * 32;
        const int n0 = wn * 64;

#pragma unroll
        for (int ks = 0; ks < 4; ks++) {
            const int chk = 2 * ks + lsel;
            uint32_t a[2][4];
#pragma unroll
            for (int mt = 0; mt < 2; mt++) {
                int r = m0 + mt * 16 + lrow;
                ldsm_x4(ab + sw128((uint32_t)(r * 128 + chk * 16)),
                        a[mt][0], a[mt][1], a[mt][2], a[mt][3]);
            }
            uint32_t blo[8], bhi[8];
#pragma unroll
            for (int p = 0; p < 4; p++) {
                int r = n0 + p * 16 + lrow;
                uint32_t r0, r1, r2, r3;
                ldsm_x4(bb + sw128((uint32_t)(r * 128 + chk * 16)), r0, r1, r2, r3);
                blo[2 * p] = r0; blo[2 * p + 1] = r1;
                bhi[2 * p] = r2; bhi[2 * p + 1] = r3;
            }
#pragma unroll
            for (int mt = 0; mt < 2; mt++)
#pragma unroll
                for (int nt = 0; nt < 8; nt++)
                    mma_f16(acc[mt][nt][0], acc[mt][nt][1], acc[mt][nt][2], acc[mt][nt][3],
                            a[mt][0], a[mt][1], a[mt][2], a[mt][3], blo[nt], bhi[nt]);
        }

        s_cur = (s_cur == NSTAGE - 1) ? 0 : s_cur + 1;
        s_nxt = (s_nxt == NSTAGE - 1) ? 0 : s_nxt + 1;
    }

    const int mbase = bm + wm * 32 + (lane >> 2);
    const int nbase = bn + wn * 64 + 2 * (lane & 3);
    if (Ch) {
#pragma unroll
        for (int mt = 0; mt < 2; mt++)
#pragma unroll
            for (int nt = 0; nt < 8; nt++) {
                __half* p0 = Ch + (size_t)(mbase + mt * 16) * N + nbase + nt * 8;
                __half* p1 = Ch + (size_t)(mbase + mt * 16 + 8) * N + nbase + nt * 8;
                *(__half2*)p0 = __floats2half2_rn(acc[mt][nt][0], acc[mt][nt][1]);
                *(__half2*)p1 = __floats2half2_rn(acc[mt][nt][2], acc[mt][nt][3]);
            }
    } else {
#pragma unroll
        for (int mt = 0; mt < 2; mt++)
#pragma unroll
            for (int nt = 0; nt < 8; nt++) {
                float* p0 = Cf + (size_t)(mbase + mt * 16) * N + nbase + nt * 8;
                float* p1 = Cf + (size_t)(mbase + mt * 16 + 8) * N + nbase + nt * 8;
                *(float2*)p0 = make_float2(acc[mt][nt][0], acc[mt][nt][1]);
                *(float2*)p1 = make_float2(acc[mt][nt][2], acc[mt][nt][3]);
            }
    }
}

// ---------------------------------------------------------------------------
// Flash attention, fp16 HMMA + f16x2 exp2, online softmax.
// Grid (S/128, H, B), 256 threads = 8 warps, warp = 16 q rows (FBQ=128).
// smem: Q 2x16KB | K 2 stages x 16KB | V 2 stages x 16KB = 96KB.
// Halves K/V L2 traffic vs FBQ=64.
// ---------------------------------------------------------------------------
#define FBQ 128
#define FBK 64
#define NKT (KSEQ / FBK)         // 32
#define FQ_OFF 0
#define FK_OFF 32768
#define FV_OFF 65536
#define FLASH_SMEM 98304

__global__ __launch_bounds__(256) void flash_f16()
{
    extern __shared__ char smem[];
    const uint32_t sbase = smem_u32(smem);
    const int tid = threadIdx.x;
    const int wid = tid >> 5;     // 0..7 -> q rows wid*16
    const int lane = tid & 31;
    const int qb = blockIdx.x;
    const int h  = blockIdx.y;
    const int b  = blockIdx.z;
    const int q0 = qb * FBQ;

    const char* qkvb = (const char*)g_qkv16;
    const size_t rowB = (size_t)KQKV * 2;

    // ---- Q load: 128 rows x 256B -> 2 chunks x 16KB ----
    {
        const size_t base = (size_t)(b * KSEQ + q0) * rowB + (size_t)h * 256;
#pragma unroll
        for (int i = 0; i < 8; i++) {
            int u = i * 256 + tid;
            int row = u >> 4, c16 = u & 15;
            uint32_t dst = sbase + FQ_OFF + (uint32_t)(c16 >> 3) * 16384
                         + sw128((uint32_t)(row * 128 + (c16 & 7) * 16));
            CPA16(dst, qkvb + base + (size_t)row * rowB + c16 * 16);
        }
    }
    // ---- K/V tile: 64 rows x 256B -> 2 chunks x 8KB per stage ----
    auto load_kv = [&](int kb) {
        const uint32_t st = (uint32_t)(kb & 1) * 16384;
        const size_t kbase = (size_t)(b * KSEQ + kb * FBK) * rowB + (size_t)(KNH + h) * 256;
        const size_t vbase = (size_t)(b * KSEQ + kb * FBK) * rowB + (size_t)(2 * KNH + h) * 256;
#pragma unroll
        for (int i = 0; i < 4; i++) {
            int u = i * 256 + tid;
            int row = u >> 4, c16 = u & 15;
            uint32_t off = (uint32_t)(c16 >> 3) * 8192
                         + sw128((uint32_t)(row * 128 + (c16 & 7) * 16));
            CPA16(sbase + FK_OFF + st + off, qkvb + kbase + (size_t)row * rowB + c16 * 16);
        }
#pragma unroll
        for (int i = 0; i < 4; i++) {
            int u = i * 256 + tid;
            int row = u >> 4, c16 = u & 15;
            uint32_t off = (uint32_t)(c16 >> 3) * 8192
                         + sw128((uint32_t)(row * 128 + (c16 & 7) * 16));
            CPA16(sbase + FV_OFF + st + off, qkvb + vbase + (size_t)row * rowB + c16 * 16);
        }
        asm volatile("cp.async.commit_group;" ::: "memory");
    };

    load_kv(0);
    load_kv(1);

    float o[17][4];
#pragma unroll
    for (int t = 0; t < 17; t++)
#pragma unroll
        for (int q = 0; q < 4; q++) o[t][q] = 0.f;
    float m0 = -1e30f, m1 = -1e30f;

    const float sl2e = 1.4426950408889634f * 0.08838834764831845f;
    const int lrow = lane & 15;
    const int lsel = lane >> 4;
    const uint32_t ones_b = (lane < 4) ? 0x3C003C00u : 0u;

#pragma unroll 1
    for (int kb = 0; kb < NKT; kb++) {
        if (kb + 1 < NKT) { asm volatile("cp.async.wait_group 1;" ::: "memory"); }
        else              { asm volatile("cp.async.wait_group 0;" ::: "memory"); }
        __syncthreads();

        const uint32_t kbuf = sbase + FK_OFF + (uint32_t)(kb & 1) * 16384;
        const uint32_t vbuf = sbase + FV_OFF + (uint32_t)(kb & 1) * 16384;
        const uint32_t qbuf = sbase + FQ_OFF;

        float s[8][4];
#pragma unroll
        for (int nt = 0; nt < 8; nt++)
#pragma unroll
            for (int q = 0; q < 4; q++) s[nt][q] = 0.f;

#pragma unroll
        for (int ks = 0; ks < 8; ks++) {
            const uint32_t qchko = (uint32_t)(ks >> 2) * 16384;
            const uint32_t kchko = (uint32_t)(ks >> 2) * 8192;
            const int chk = 2 * (ks & 3) + lsel;
            uint32_t a0, a1, a2, a3;
            {
                int r = wid * 16 + lrow;
                ldsm_x4(qbuf + qchko + sw128((uint32_t)(r * 128 + chk * 16)), a0, a1, a2, a3);
            }
            uint32_t blo[8], bhi[8];
#pragma unroll
            for (int p = 0; p < 4; p++) {
                int r = p * 16 + lrow;
                uint32_t r0, r1, r2, r3;
                ldsm_x4(kbuf + kchko + sw128((uint32_t)(r * 128 + chk * 16)), r0, r1, r2, r3);
                blo[2 * p] = r0; blo[2 * p + 1] = r1;
                bhi[2 * p] = r2; bhi[2 * p + 1] = r3;
            }
#pragma unroll
            for (int nt = 0; nt < 8; nt++)
                mma_f16(s[nt][0], s[nt][1], s[nt][2], s[nt][3],
                        a0, a1, a2, a3, blo[nt], bhi[nt]);
        }

        float mx0 = -1e30f, mx1 = -1e30f;
#pragma unroll
        for (int nt = 0; nt < 8; nt++) {
            s[nt][0] *= sl2e; s[nt][1] *= sl2e;
            s[nt][2] *= sl2e; s[nt][3] *= sl2e;
            mx0 = fmaxf(mx0, fmaxf(s[nt][0], s[nt][1]));
            mx1 = fmaxf(mx1, fmaxf(s[nt][2], s[nt][3]));
        }
        mx0 = fmaxf(mx0, __shfl_xor_sync(0xffffffffu, mx0, 1));
        mx0 = fmaxf(mx0, __shfl_xor_sync(0xffffffffu, mx0, 2));
        mx1 = fmaxf(mx1, __shfl_xor_sync(0xffffffffu, mx1, 1));
        mx1 = fmaxf(mx1, __shfl_xor_sync(0xffffffffu, mx1, 2));
        const float mn0 = fmaxf(m0, mx0);
        const float mn1 = fmaxf(m1, mx1);
        const float corr0 = ex2f(m0 - mn0);
        const float corr1 = ex2f(m1 - mn1);
        m0 = mn0; m1 = mn1;
#pragma unroll
        for (int t = 0; t < 17; t++) {
            o[t][0] *= corr0; o[t][1] *= corr0;
            o[t][2] *= corr1; o[t][3] *= corr1;
        }
        uint32_t p01[8], p23[8];
#pragma unroll
        for (int nt = 0; nt < 8; nt++) {
            __half2 h0 = h2exp2(__floats2half2_rn(s[nt][0] - mn0, s[nt][1] - mn0));
            __half2 h1 = h2exp2(__floats2half2_rn(s[nt][2] - mn1, s[nt][3] - mn1));
            p01[nt] = *(uint32_t*)&h0;
            p23[nt] = *(uint32_t*)&h1;
        }

        const int grp  = lane >> 3;
        const int glr  = lane & 7;
#pragma unroll
        for (int ks = 0; ks < 4; ks++) {
            const uint32_t a0 = p01[2 * ks],     a1 = p23[2 * ks];
            const uint32_t a2 = p01[2 * ks + 1], a3 = p23[2 * ks + 1];
            const int key = 16 * ks + (grp & 1) * 8 + glr;
#pragma unroll
            for (int pp = 0; pp < 8; pp++) {
                const int d = pp * 16 + (grp >> 1) * 8;
                const uint32_t addr = vbuf + (uint32_t)(d >> 6) * 8192
                                    + sw128((uint32_t)(key * 128 + (d & 63) * 2));
                uint32_t r0, r1, r2, r3;
                ldsm_x4t(addr, r0, r1, r2, r3);
                mma_f16(o[2 * pp][0], o[2 * pp][1], o[2 * pp][2], o[2 * pp][3],
                        a0, a1, a2, a3, r0, r1);
                mma_f16(o[2 * pp + 1][0], o[2 * pp + 1][1], o[2 * pp + 1][2], o[2 * pp + 1][3],
                        a0, a1, a2, a3, r2, r3);
            }
            mma_f16(o[16][0], o[16][1], o[16][2], o[16][3],
                    a0, a1, a2, a3, ones_b, ones_b);
        }

        __syncthreads();
        if (kb + 2 < NKT) load_kv(kb + 2);
    }

    // ---- Epilogue: normalize, write fp16 [hi|lo] into g_comb2 ----
    const int src = lane & ~3;
    const float l0 = __shfl_sync(0xffffffffu, o[16][0], src);
    const float l1 = __shfl_sync(0xffffffffu, o[16][2], src);
    const float inv0 = 1.f / l0;
    const float inv1 = 1.f / l1;

    const int gr0 = b * KSEQ + q0 + wid * 16 + (lane >> 2);
    const int col0 = h * KHD + 2 * (lane & 3);
#pragma unroll
    for (int t = 0; t < 16; t++) {
#pragma unroll
        for (int rr = 0; rr < 2; rr++) {
            float v0 = o[t][2 * rr + 0] * (rr ? inv1 : inv0);
            float v1 = o[t][2 * rr + 1] * (rr ? inv1 : inv0);
            __half h0 = __float2half_rn(v0);
            __half h1 = __float2half_rn(v1);
            __half l0h = __float2half_rn(v0 - __half2float(h0));
            __half l1h = __float2half_rn(v1 - __half2float(h1));
            uint32_t hp = (uint32_t)__half_as_ushort(h0)
                        | ((uint32_t)__half_as_ushort(h1) << 16);
            uint32_t lp = (uint32_t)__half_as_ushort(l0h)
                        | ((uint32_t)__half_as_ushort(l1h) << 16);
            __half* dst = g_comb2 + (size_t)(gr0 + rr * 8) * K2 + col0 + t * 8;
            *(uint32_t*)(dst)        = hp;
            *(uint32_t*)(dst + KDIM) = lp;
        }
    }
}

// ---------------------------------------------------------------------------
extern "C" void kernel_launch(void* const* d_in, const int* in_sizes, int n_in,
                              void* d_out, int out_size)
{
    (void)in_sizes; (void)n_in; (void)out_size;
    const float* x     = (const float*)d_in[0];
    const float* w_qkv = (const float*)d_in[1];
    const float* w_out = (const float*)d_in[2];
    float* out = (float*)d_out;

    __half* qkv16_p; cudaGetSymbolAddress((void**)&qkv16_p, g_qkv16);
    __half* x16_p;   cudaGetSymbolAddress((void**)&x16_p,   g_x16);
    __half* wq16_p;  cudaGetSymbolAddress((void**)&wq16_p,  g_wq16);
    __half* cb_p;    cudaGetSymbolAddress((void**)&cb_p,    g_comb2);
    __half* wo_p;    cudaGetSymbolAddress((void**)&wo_p,    g_wout2);

    // 0) Converts / dup
    {
        int t4;
        t4 = KROWS * KDIM / 4;
        conv_f16<<<(t4 + 255) / 256, 256>>>(x, x16_p, t4);
        t4 = KQKV * KDIM / 4;
        conv_f16<<<(t4 + 255) / 256, 256>>>(w_qkv, wq16_p, t4);
        t4 = KMODEL * KDIM / 4;
        dup_f16<<<(t4 + 255) / 256, 256>>>(w_out, wo_p, t4, KDIM);
    }

    cudaFuncSetAttribute(gemm_hmma,
                         cudaFuncAttributeMaxDynamicSharedMemorySize, GEMM_SMEM);

    // 1) QKV projection (fp16 HMMA, K=2048) -> fp16 g_qkv16
    {
        dim3 grid(KQKV / BN, KROWS / BM);
        gemm_hmma<<<grid, 256, GEMM_SMEM>>>(
            (const uint16_t*)x16_p, (const uint16_t*)wq16_p,
            nullptr, qkv16_p, KQKV, KDIM);
    }

    // 2) Flash attention (fp16 HMMA, FBQ=128) -> fp16 [hi|lo] g_comb2
    {
        cudaFuncSetAttribute(flash_f16,
                             cudaFuncAttributeMaxDynamicSharedMemorySize, FLASH_SMEM);
        dim3 grid(KSEQ / FBQ, KNH, KBATCH);
        flash_f16<<<grid, 256, FLASH_SMEM>>>();
    }

    // 3) Output projection (fp16 2-term split, K=4096) -> fp32 out
    {
        dim3 grid(KMODEL / BN, KROWS / BM);
        gemm_hmma<<<grid, 256, GEMM_SMEM>>>(
            (const uint16_t*)cb_p, (const uint16_t*)wo_p,
            out, nullptr, KMODEL, K2);
    }
}